// round 14
// baseline (speedup 1.0000x reference)
#include <cuda_runtime.h>
#include <cuda_bf16.h>
#include <mma.h>
#include <math.h>
#include <stdint.h>

using namespace nvcuda;

#define NB 2
#define CH 256
#define SV 32768L
#define NH 4
#define HD 64
#define SCALE_INV 0.0625f
#define EPS 1e-6f

__device__ __forceinline__ unsigned pack2(float a, float b) {
    __nv_bfloat162 t = __floats2bfloat162_rn(a, b);
    return *reinterpret_cast<unsigned*>(&t);
}

// ---------------- scratch ----------------
__device__ __align__(16) float g_attn   [NB * 256L * SV];
__device__ __align__(16) float g_praw   [NB * 256 * 512];
__device__ __align__(16) float g_pnorm  [NB * 256 * 512];
__device__ __align__(16) __nv_bfloat16 g_xB    [NB * 256L * SV];
__device__ __align__(16) __nv_bfloat16 g_qkvB  [NB * 768L * SV];
__device__ __align__(16) __nv_bfloat16 g_attnB [NB * 256L * SV];
__device__ __align__(16) __nv_bfloat16 g_ghi   [NB * 256L * SV];
__device__ __align__(16) __nv_bfloat16 g_glo   [NB * 256L * SV];
__device__ __align__(16) __nv_bfloat16 g_pooledB[NB * 256 * 512];
__device__ __align__(16) __nv_bfloat16 g_q2T   [NB * 4L * SV * 64];
__device__ __align__(16) __nv_bfloat16 g_kvT   [NB * 8L * 512 * 64];
__device__ __align__(16) __nv_bfloat16 g_Wqkv2B[NB * 768 * 256];
__device__ __align__(16) __nv_bfloat16 g_Wq2B  [NB * 256 * 256];
__device__ __align__(16) __nv_bfloat16 g_WkvB  [512 * 256];
__device__ __align__(16) __nv_bfloat16 g_WprojB[256 * 768];
__device__ float g_qkvb2[NB * 768];
__device__ float g_qb2  [NB * 256];
__device__ float g_part [NB * 2048 * 2];
__device__ float g_part2[NB * 64 * 2];
__device__ float g_aff  [6 * NB * 256];

// ---------------- cp.async ----------------
__device__ __forceinline__ void cp16(void* dst, const void* src) {
    unsigned d = (unsigned)__cvta_generic_to_shared(dst);
    asm volatile("cp.async.cg.shared.global [%0], [%1], 16;\n" :: "r"(d), "l"(src));
}
#define CP_COMMIT asm volatile("cp.async.commit_group;\n" ::: "memory")
#define CP_WAIT1  asm volatile("cp.async.wait_group 1;\n" ::: "memory")
#define CP_WAIT0  asm volatile("cp.async.wait_group 0;\n" ::: "memory")

// =========================================================================
// reductions / affine / conversions
// =========================================================================
__global__ void reduce1x_kernel(const float* __restrict__ buf, long per4,
                                float* __restrict__ part, __nv_bfloat16* __restrict__ outB) {
    int n = blockIdx.y;
    const float4* p = reinterpret_cast<const float4*>(buf) + (size_t)n * per4;
    uint2* ob = reinterpret_cast<uint2*>(outB) + (size_t)n * per4;
    float s = 0.f, ss = 0.f;
    for (long i = (long)blockIdx.x * blockDim.x + threadIdx.x; i < per4;
         i += (long)gridDim.x * blockDim.x) {
        float4 v = p[i];
        s  += v.x + v.y + v.z + v.w;
        ss += v.x*v.x + v.y*v.y + v.z*v.z + v.w*v.w;
        uint2 r;
        r.x = pack2(v.x, v.y);
        r.y = pack2(v.z, v.w);
        ob[i] = r;
    }
    for (int o = 16; o; o >>= 1) {
        s  += __shfl_down_sync(0xffffffffu, s, o);
        ss += __shfl_down_sync(0xffffffffu, ss, o);
    }
    __shared__ float sh[64];
    int w = threadIdx.x >> 5;
    if ((threadIdx.x & 31) == 0) { sh[w] = s; sh[32 + w] = ss; }
    __syncthreads();
    if (threadIdx.x < 32) {
        int nw = blockDim.x >> 5;
        s  = (threadIdx.x < nw) ? sh[threadIdx.x]      : 0.f;
        ss = (threadIdx.x < nw) ? sh[32 + threadIdx.x] : 0.f;
        for (int o = 16; o; o >>= 1) {
            s  += __shfl_down_sync(0xffffffffu, s, o);
            ss += __shfl_down_sync(0xffffffffu, ss, o);
        }
        if (threadIdx.x == 0) {
            part[((size_t)n * gridDim.x + blockIdx.x) * 2 + 0] = s;
            part[((size_t)n * gridDim.x + blockIdx.x) * 2 + 1] = ss;
        }
    }
}

__global__ void reduce1_kernel(const float* __restrict__ buf, long per4, float* __restrict__ part) {
    int n = blockIdx.y;
    const float4* p = reinterpret_cast<const float4*>(buf) + (size_t)n * per4;
    float s = 0.f, ss = 0.f;
    for (long i = (long)blockIdx.x * blockDim.x + threadIdx.x; i < per4;
         i += (long)gridDim.x * blockDim.x) {
        float4 v = p[i];
        s  += v.x + v.y + v.z + v.w;
        ss += v.x*v.x + v.y*v.y + v.z*v.z + v.w*v.w;
    }
    for (int o = 16; o; o >>= 1) {
        s  += __shfl_down_sync(0xffffffffu, s, o);
        ss += __shfl_down_sync(0xffffffffu, ss, o);
    }
    __shared__ float sh[64];
    int w = threadIdx.x >> 5;
    if ((threadIdx.x & 31) == 0) { sh[w] = s; sh[32 + w] = ss; }
    __syncthreads();
    if (threadIdx.x < 32) {
        int nw = blockDim.x >> 5;
        s  = (threadIdx.x < nw) ? sh[threadIdx.x]      : 0.f;
        ss = (threadIdx.x < nw) ? sh[32 + threadIdx.x] : 0.f;
        for (int o = 16; o; o >>= 1) {
            s  += __shfl_down_sync(0xffffffffu, s, o);
            ss += __shfl_down_sync(0xffffffffu, ss, o);
        }
        if (threadIdx.x == 0) {
            part[((size_t)n * gridDim.x + blockIdx.x) * 2 + 0] = s;
            part[((size_t)n * gridDim.x + blockIdx.x) * 2 + 1] = ss;
        }
    }
}

__global__ void stats2affine_kernel(const float* __restrict__ part, int nb,
                                    const float* __restrict__ w, const float* __restrict__ b,
                                    float* __restrict__ a, float* __restrict__ d,
                                    float inv_cnt) {
    int n = blockIdx.x, tid = threadIdx.x;
    float s = 0.f, ss = 0.f;
    for (int i = tid; i < nb; i += 256) {
        s  += part[((size_t)n * nb + i) * 2 + 0];
        ss += part[((size_t)n * nb + i) * 2 + 1];
    }
    for (int o = 16; o; o >>= 1) {
        s  += __shfl_down_sync(0xffffffffu, s, o);
        ss += __shfl_down_sync(0xffffffffu, ss, o);
    }
    __shared__ float sh[16];
    __shared__ float sm_mean, sm_rstd;
    int wp = tid >> 5;
    if ((tid & 31) == 0) { sh[wp] = s; sh[8 + wp] = ss; }
    __syncthreads();
    if (tid < 32) {
        s  = (tid < 8) ? sh[tid]     : 0.f;
        ss = (tid < 8) ? sh[8 + tid] : 0.f;
        for (int o = 4; o; o >>= 1) {
            s  += __shfl_down_sync(0xffffffffu, s, o);
            ss += __shfl_down_sync(0xffffffffu, ss, o);
        }
        if (tid == 0) {
            float mean = s * inv_cnt;
            float var  = ss * inv_cnt - mean * mean;
            sm_mean = mean;
            sm_rstd = rsqrtf(var + EPS);
        }
    }
    __syncthreads();
    float mean = sm_mean, rstd = sm_rstd;
    a[n * CH + tid] = w[tid] * rstd;
    d[n * CH + tid] = b[tid] - mean * rstd * w[tid];
}

__global__ void convert_plain_kernel(const float* __restrict__ x, __nv_bfloat16* __restrict__ out) {
    size_t i8 = (size_t)blockIdx.x * blockDim.x + threadIdx.x;
    const float4* p = reinterpret_cast<const float4*>(x) + i8 * 2;
    float4 v0 = p[0], v1 = p[1];
    uint4 u;
    u.x = pack2(v0.x, v0.y);
    u.y = pack2(v0.z, v0.w);
    u.z = pack2(v1.x, v1.y);
    u.w = pack2(v1.z, v1.w);
    reinterpret_cast<uint4*>(out)[i8] = u;
}

__global__ void fold_kernel(const float* __restrict__ W, const float* __restrict__ bsrc,
                            const float* __restrict__ A, const float* __restrict__ D,
                            __nv_bfloat16* __restrict__ W2, float* __restrict__ b2, int Mrows) {
    int m = blockIdx.x, n = blockIdx.y, tid = threadIdx.x;
    float w = W[(size_t)m * 256 + tid];
    float aa = A[n * 256 + tid], dd = D[n * 256 + tid];
    W2[((size_t)n * Mrows + m) * 256 + tid] = __float2bfloat16(w * aa);
    float pr = w * dd;
    for (int o = 16; o; o >>= 1) pr += __shfl_down_sync(0xffffffffu, pr, o);
    __shared__ float sh[8];
    if ((tid & 31) == 0) sh[tid >> 5] = pr;
    __syncthreads();
    if (tid == 0) {
        float t = 0.f;
        #pragma unroll
        for (int i = 0; i < 8; i++) t += sh[i];
        b2[n * Mrows + m] = bsrc[m] + t;
    }
}

__global__ void apply_pool_affine_kernel(const float* __restrict__ praw,
                                         const float* __restrict__ a, const float* __restrict__ d,
                                         float* __restrict__ pnorm) {
    size_t i4 = (size_t)blockIdx.x * blockDim.x + threadIdx.x;
    int c = (int)((i4 >> 7) & 255);
    int n = (int)(i4 >> 15);
    float aa = a[n * CH + c], dd = d[n * CH + c];
    float4 v = reinterpret_cast<const float4*>(praw)[i4];
    v.x = fmaf(aa, v.x, dd); v.y = fmaf(aa, v.y, dd);
    v.z = fmaf(aa, v.z, dd); v.w = fmaf(aa, v.w, dd);
    reinterpret_cast<float4*>(pnorm)[i4] = v;
}

__global__ void convert_pooled_kernel(const float* __restrict__ pooled,
                                      const float* __restrict__ a, const float* __restrict__ d,
                                      __nv_bfloat16* __restrict__ out) {
    size_t i4 = (size_t)blockIdx.x * blockDim.x + threadIdx.x;
    int c = (int)((i4 >> 7) & 255);
    int n = (int)(i4 >> 15);
    float aa = a[n * CH + c], dd = d[n * CH + c];
    float4 v = reinterpret_cast<const float4*>(pooled)[i4];
    uint2 r;
    r.x = pack2(fmaf(aa, v.x, dd), fmaf(aa, v.y, dd));
    r.y = pack2(fmaf(aa, v.z, dd), fmaf(aa, v.w, dd));
    reinterpret_cast<uint2*>(out)[i4] = r;
}

__global__ void convert_weights_kernel(
    const float* __restrict__ kv_w, const float* __restrict__ proj_w,
    __nv_bfloat16* __restrict__ Wkv, __nv_bfloat16* __restrict__ Wproj) {
    int idx = blockIdx.x * blockDim.x + threadIdx.x;
    const int T1 = 512 * 256, T2 = T1 + 256 * 768;
    if (idx < T1) {
        Wkv[idx] = __float2bfloat16(kv_w[idx]);
    } else if (idx < T2) {
        int j = idx - T1;
        int m = j / 768, k = j % 768;
        float v = proj_w[m * 256 + (k & 255)];
        __nv_bfloat16 hi = __float2bfloat16(v);
        if (k >= 256 && k < 512) hi = __float2bfloat16(v - __bfloat162float(hi));
        Wproj[j] = hi;
    }
}

// =========================================================================
// wgemm3: BM=128, BN=128, BK=64, 3-stage cp.async, 256 threads, 2 blocks/SM.
// =========================================================================
#define WG_A_STG 9216   /* 128*72 elems */
#define WG_B_STG 8704   /* 64*136 elems */
#define WG_SMEM (3 * (WG_A_STG + WG_B_STG) * 2)   /* 107520 B */

template<int MODE>
__global__ void __launch_bounds__(256, 2) wgemm3_kernel(
    const __nv_bfloat16* __restrict__ A,
    const __nv_bfloat16* __restrict__ B0, const __nv_bfloat16* __restrict__ B1,
    const float* __restrict__ bias,
    float* __restrict__ outF, __nv_bfloat16* __restrict__ outB,
    int M, int S, int KT, float qScale, long aStride, int biasStride) {
    extern __shared__ __align__(16) char dsm[];
    __nv_bfloat16* As = (__nv_bfloat16*)dsm;                       // 3 x [128*72]
    __nv_bfloat16* Bs = (__nv_bfloat16*)(dsm + 3 * WG_A_STG * 2);  // 3 x [64*136]
    float* Cs = (float*)dsm;                                       // [128][132]

    int tid = threadIdx.x, warp = tid >> 5;
    int wm = warp >> 2, wn = warp & 3;
    int m0 = blockIdx.x * 128;
    int s0 = blockIdx.y * 128;
    int z  = blockIdx.z;

    const __nv_bfloat16* Az = A + (size_t)z * aStride;
    const float* biasz = bias + (size_t)z * biasStride;
    const __nv_bfloat16* Bb0 = B0 + (size_t)z * 256 * S;
    const __nv_bfloat16* Bb1 = B1 + (size_t)z * 256 * S;

    wmma::fragment<wmma::accumulator, 16, 16, 16, float> acc[4][2];
    #pragma unroll
    for (int i = 0; i < 4; i++)
        #pragma unroll
        for (int j = 0; j < 2; j++) wmma::fill_fragment(acc[i][j], 0.f);

    const int NIT = KT >> 6;

    auto prefetch = [&](int it, int buf) {
        int ktL = it * 64;
        // A: 128 rows x 64 K -> 1024 x 16B chunks
        #pragma unroll
        for (int i = 0; i < 4; i++) {
            int c = tid + i * 256;
            int r = c >> 3, q = (c & 7) * 8;
            cp16(As + buf * WG_A_STG + r * 72 + q,
                 Az + (size_t)(m0 + r) * KT + ktL + q);
        }
        // B: 64 rows x 128 cols -> 1024 x 16B chunks
        const __nv_bfloat16* Bp = (ktL < 512) ? Bb0 : Bb1;
        int krow = ktL & 255;
        #pragma unroll
        for (int i = 0; i < 4; i++) {
            int c = tid + i * 256;
            int r = c >> 4, q = (c & 15) * 8;
            cp16(Bs + buf * WG_B_STG + r * 136 + q,
                 Bp + (size_t)(krow + r) * S + s0 + q);
        }
    };

    prefetch(0, 0); CP_COMMIT;
    if (NIT > 1) { prefetch(1, 1); CP_COMMIT; }

    int buf = 0;
    for (int it = 0; it < NIT; it++) {
        if (it + 1 < NIT) CP_WAIT1; else CP_WAIT0;
        __syncthreads();
        #pragma unroll
        for (int ks = 0; ks < 4; ks++) {
            wmma::fragment<wmma::matrix_a, 16, 16, 16, __nv_bfloat16, wmma::row_major> af[4];
            #pragma unroll
            for (int i = 0; i < 4; i++)
                wmma::load_matrix_sync(af[i], As + buf * WG_A_STG + (wm * 64 + i * 16) * 72 + ks * 16, 72);
            wmma::fragment<wmma::matrix_b, 16, 16, 16, __nv_bfloat16, wmma::row_major> bf[2];
            #pragma unroll
            for (int j = 0; j < 2; j++)
                wmma::load_matrix_sync(bf[j], Bs + buf * WG_B_STG + (ks * 16) * 136 + wn * 32 + j * 16, 136);
            #pragma unroll
            for (int i = 0; i < 4; i++)
                #pragma unroll
                for (int j = 0; j < 2; j++)
                    wmma::mma_sync(acc[i][j], af[i], bf[j], acc[i][j]);
        }
        if (it + 2 < NIT) {
            prefetch(it + 2, (buf + 2) % 3);
            CP_COMMIT;
        }
        buf = (buf + 1) % 3;
    }

    __syncthreads();

    if (MODE == 0) {
        #pragma unroll
        for (int i = 0; i < 4; i++)
            #pragma unroll
            for (int j = 0; j < 2; j++)
                wmma::store_matrix_sync(Cs + (wm * 64 + i * 16) * 132 + wn * 32 + j * 16,
                                        acc[i][j], 132, wmma::mem_row_major);
        __syncthreads();
        float* Ob = outF + ((size_t)z * M + m0) * S;
        #pragma unroll
        for (int it = 0; it < 16; it++) {
            int idx = tid + it * 256;
            int r = idx >> 5, c4 = idx & 31;
            float bv = biasz[m0 + r];
            float4 v = *reinterpret_cast<const float4*>(&Cs[r * 132 + c4 * 4]);
            v.x += bv; v.y += bv; v.z += bv; v.w += bv;
            *reinterpret_cast<float4*>(&Ob[(size_t)r * S + s0 + c4 * 4]) = v;
        }
    } else {
        #pragma unroll
        for (int i = 0; i < 4; i++)
            #pragma unroll
            for (int j = 0; j < 2; j++)
                wmma::store_matrix_sync(Cs + (wn * 32 + j * 16) * 136 + wm * 64 + i * 16,
                                        acc[i][j], 136, wmma::mem_col_major);
        __syncthreads();

        int dg = tid & 15;
        int gmb = m0 + dg * 8;
        float bias8[8];
        #pragma unroll
        for (int e = 0; e < 8; e++) bias8[e] = biasz[gmb + e];

        float sc;
        int db = gmb & 63;
        __nv_bfloat16* hbase;
        if (MODE == 1) {
            int hb = gmb >> 6;
            sc = qScale;
            hbase = outB + ((size_t)(z * (M >> 6) + hb) * S + s0) * 64 + db;
        } else {
            int sel = gmb >> 8, head = (gmb >> 6) & 3;
            sc = (sel == 0) ? qScale : 1.f;
            hbase = outB + (((size_t)(z * 3 + sel) * 4 + head) * 512) * 4096 + db;
        }

        #pragma unroll
        for (int it = 0; it < 8; it++) {
            int sl = it * 16 + (tid >> 4);
            float4 lo = *reinterpret_cast<const float4*>(&Cs[sl * 136 + dg * 8]);
            float4 hi = *reinterpret_cast<const float4*>(&Cs[sl * 136 + dg * 8 + 4]);
            float f[8] = {lo.x, lo.y, lo.z, lo.w, hi.x, hi.y, hi.z, hi.w};
            #pragma unroll
            for (int e = 0; e < 8; e++) f[e] = (f[e] + bias8[e]) * sc;
            uint4 u;
            u.x = pack2(f[0], f[1]);
            u.y = pack2(f[2], f[3]);
            u.z = pack2(f[4], f[5]);
            u.w = pack2(f[6], f[7]);
            size_t off;
            if (MODE == 1) {
                off = (size_t)sl * 64;
            } else {
                int s = s0 + sl;
                int d5 = s & 31, w5 = (s >> 5) & 31, h5 = s >> 10;
                int window = ((h5 >> 2) * 8 + (w5 >> 2)) * 8 + (d5 >> 2);
                int token  = (((h5 & 3) * 4 + (w5 & 3)) * 4 + (d5 & 3));
                off = (size_t)window * 4096 + token * 64;
            }
            *reinterpret_cast<uint4*>(hbase + off) = u;
        }
    }
}

// =========================================================================
// Local windowed attention (wmma, no-max softmax) + pool sums + gn partials
// =========================================================================
__global__ void __launch_bounds__(128) local_attn_w_kernel(
    const __nv_bfloat16* __restrict__ qkvB, const float* __restrict__ x,
    float* __restrict__ attn, float* __restrict__ praw, float* __restrict__ part) {
    __shared__ __align__(16) __nv_bfloat16 QP[64 * 72];
    __shared__ __align__(16) __nv_bfloat16 Ks[64 * 72];
    __shared__ __align__(16) __nv_bfloat16 Vs[64 * 72];
    __shared__ __align__(16) float Sf[64 * 68];
    __shared__ float linv[64];
    __shared__ float rs[4], rss[4];

    int w = blockIdx.x, head = blockIdx.y, n = blockIdx.z;
    int tid = threadIdx.x, warp = tid >> 5;

    size_t base = (((size_t)(n * 3) * 4 + head) * 512 + w) * 4096;
    size_t step = (size_t)4 * 512 * 4096;
    const uint4* Qg = (const uint4*)(qkvB + base);
    const uint4* Kg = (const uint4*)(qkvB + base + step);
    const uint4* Vg = (const uint4*)(qkvB + base + 2 * step);

    #pragma unroll
    for (int i = 0; i < 4; i++) {
        int c = tid + i * 128;
        int r = c >> 3, q = c & 7;
        ((uint4*)(QP + r * 72))[q] = Qg[c];
        ((uint4*)(Ks + r * 72))[q] = Kg[c];
        ((uint4*)(Vs + r * 72))[q] = Vg[c];
    }
    __syncthreads();

    {
        int m = warp * 16;
        wmma::fragment<wmma::accumulator, 16, 16, 16, float> acc[4];
        #pragma unroll
        for (int j = 0; j < 4; j++) wmma::fill_fragment(acc[j], 0.f);
        #pragma unroll
        for (int kd = 0; kd < 4; kd++) {
            wmma::fragment<wmma::matrix_a, 16, 16, 16, __nv_bfloat16, wmma::row_major> af;
            wmma::load_matrix_sync(af, QP + m * 72 + kd * 16, 72);
            #pragma unroll
            for (int j = 0; j < 4; j++) {
                wmma::fragment<wmma::matrix_b, 16, 16, 16, __nv_bfloat16, wmma::col_major> bf;
                wmma::load_matrix_sync(bf, Ks + (j * 16) * 72 + kd * 16, 72);
                wmma::mma_sync(acc[j], af, bf, acc[j]);
            }
        }
        #pragma unroll
        for (int j = 0; j < 4; j++)
            wmma::store_matrix_sync(Sf + m * 68 + j * 16, acc[j], 68, wmma::mem_row_major);
    }
    __syncthreads();

    {
        int r = tid >> 1, hf = tid & 1;
        const float* srow = Sf + r * 68 + hf * 32;
        float ls = 0.f;
        __nv_bfloat16* prow = QP + r * 72 + hf * 32;
        #pragma unroll
        for (int j = 0; j < 32; j++) {
            float p = __expf(srow[j]);
            ls += p;
            prow[j] = __float2bfloat16(p);
        }
        ls += __shfl_xor_sync(0xffffffffu, ls, 1);
        if (hf == 0) linv[r] = 1.f / ls;
    }
    __syncthreads();

    {
        int m = warp * 16;
        wmma::fragment<wmma::accumulator, 16, 16, 16, float> acc[4];
        #pragma unroll
        for (int j = 0; j < 4; j++) wmma::fill_fragment(acc[j], 0.f);
        #pragma unroll
        for (int kk = 0; kk < 4; kk++) {
            wmma::fragment<wmma::matrix_a, 16, 16, 16, __nv_bfloat16, wmma::row_major> af;
            wmma::load_matrix_sync(af, QP + m * 72 + kk * 16, 72);
            #pragma unroll
            for (int j = 0; j < 4; j++) {
                wmma::fragment<wmma::matrix_b, 16, 16, 16, __nv_bfloat16, wmma::row_major> bf;
                wmma::load_matrix_sync(bf, Vs + (kk * 16) * 72 + j * 16, 72);
                wmma::mma_sync(acc[j], af, bf, acc[j]);
            }
        }
        #pragma unroll
        for (int j = 0; j < 4; j++)
            wmma::store_matrix_sync(Sf + m * 68 + j * 16, acc[j], 68, wmma::mem_row_major);
    }
    __syncthreads();

    int wh = w >> 6, ww = (w >> 3) & 7, wd = w & 7;
    int base_s = wh * 4096 + ww * 128 + wd * 4;
    int chb = n * 256 + head * 64;
    float s_acc = 0.f, ss_acc = 0.f;
    #pragma unroll
    for (int it = 0; it < 8; it++) {
        int idx = tid + it * 128;
        int d = idx >> 4, tg = idx & 15;
        int i_ = tg >> 2, j_ = tg & 3;
        int s = base_s + i_ * 1024 + j_ * 32;
        int t0 = tg * 4;
        size_t g = ((size_t)(chb + d)) * SV + s;
        float4 xv = *reinterpret_cast<const float4*>(x + g);
        float4 ov;
        ov.x = fmaf(Sf[(t0 + 0) * 68 + d], linv[t0 + 0], xv.x);
        ov.y = fmaf(Sf[(t0 + 1) * 68 + d], linv[t0 + 1], xv.y);
        ov.z = fmaf(Sf[(t0 + 2) * 68 + d], linv[t0 + 2], xv.z);
        ov.w = fmaf(Sf[(t0 + 3) * 68 + d], linv[t0 + 3], xv.w);
        *reinterpret_cast<float4*>(attn + g) = ov;
        float ps = ov.x + ov.y + ov.z + ov.w;
        s_acc  += ps;
        ss_acc += ov.x*ov.x + ov.y*ov.y + ov.z*ov.z + ov.w*ov.w;
        #pragma unroll
        for (int o = 8; o; o >>= 1) ps += __shfl_down_sync(0xffffffffu, ps, o);
        if ((tid & 15) == 0)
            praw[((size_t)(chb + d)) * 512 + w] = ps * (1.f / 64.f);
    }
    #pragma unroll
    for (int o = 16; o; o >>= 1) {
        s_acc  += __shfl_down_sync(0xffffffffu, s_acc, o);
        ss_acc += __shfl_down_sync(0xffffffffu, ss_acc, o);
    }
    if ((tid & 31) == 0) { rs[warp] = s_acc; rss[warp] = ss_acc; }
    __syncthreads();
    if (tid == 0) {
        size_t pi = (size_t)n * 2048 + head * 512 + w;
        part[pi * 2 + 0] = rs[0] + rs[1] + rs[2] + rs[3];
        part[pi * 2 + 1] = rss[0] + rss[1] + rss[2] + rss[3];
    }
}

// =========================================================================
// Global attention: no-max softmax, O persistent in accumulators,
// cp.async double-buffered K/V.
// =========================================================================
#define GA_SMEM 109056

__global__ void __launch_bounds__(256, 2) gattn_kernel(
    const __nv_bfloat16* __restrict__ q2T, const __nv_bfloat16* __restrict__ kvT,
    const float* __restrict__ attn,
    const float* __restrict__ A1, const float* __restrict__ D1,
    __nv_bfloat16* __restrict__ ghi, __nv_bfloat16* __restrict__ glo) {
    extern __shared__ __align__(16) char sm[];
    __nv_bfloat16* Qs = (__nv_bfloat16*)sm;
    __nv_bfloat16* Ks = Qs + 128 * 72;
    __nv_bfloat16* Vs = Ks + 2 * 64 * 72;
    __nv_bfloat16* Ps = Vs + 2 * 64 * 72;
    float* Sf   = (float*)(Ps + 128 * 72);
    float* lrow = Sf + 128 * 68;

    int tid = threadIdx.x, warp = tid >> 5;
    int h = blockIdx.y, n = blockIdx.z;
    int s0 = blockIdx.x * 128;

    const uint4* Qg = (const uint4*)(q2T + ((size_t)(n * 4 + h) * SV + s0) * 64);
    const __nv_bfloat16* Kg = kvT + ((size_t)(n * 8 + h) * 512) * 64;
    const __nv_bfloat16* Vg = kvT + ((size_t)(n * 8 + 4 + h) * 512) * 64;

    auto prefetchKV = [&](int ch, int b) {
        #pragma unroll
        for (int i = 0; i < 2; i++) {
            int idx = tid + i * 256;
            int r = idx >> 3, c = (idx & 7) * 8;
            cp16(Ks + b * 4608 + r * 72 + c, Kg + (size_t)(ch * 64 + r) * 64 + c);
            cp16(Vs + b * 4608 + r * 72 + c, Vg + (size_t)(ch * 64 + r) * 64 + c);
        }
    };

    prefetchKV(0, 0); CP_COMMIT;

    #pragma unroll
    for (int i = 0; i < 4; i++) {
        int idx = tid + i * 256;
        int r = idx >> 3, c = idx & 7;
        ((uint4*)(Qs + r * 72))[c] = Qg[r * 8 + c];
    }
    if (tid < 128) lrow[tid] = 0.f;

    int pm = warp >> 1, pn = warp & 1;
    wmma::fragment<wmma::accumulator, 16, 16, 16, float> acc_o[2][2];
    #pragma unroll
    for (int i = 0; i < 2; i++)
        #pragma unroll
        for (int j = 0; j < 2; j++) wmma::fill_fragment(acc_o[i][j], 0.f);

    for (int ch = 0; ch < 8; ch++) {
        int b = ch & 1;
        CP_WAIT0;
        __syncthreads();

        {
            int m = warp * 16;
            wmma::fragment<wmma::accumulator, 16, 16, 16, float> acc[4];
            #pragma unroll
            for (int j = 0; j < 4; j++) wmma::fill_fragment(acc[j], 0.f);
            #pragma unroll
            for (int kd = 0; kd < 4; kd++) {
                wmma::fragment<wmma::matrix_a, 16, 16, 16, __nv_bfloat16, wmma::row_major> af;
                wmma::load_matrix_sync(af, Qs + m * 72 + kd * 16, 72);
                #pragma unroll
                for (int j = 0; j < 4; j++) {
                    wmma::fragment<wmma::matrix_b, 16, 16, 16, __nv_bfloat16, wmma::col_major> bf;
                    wmma::load_matrix_sync(bf, Ks + b * 4608 + (j * 16) * 72 + kd * 16, 72);
                    wmma::mma_sync(acc[j], af, bf, acc[j]);
                }
            }
            #pragma unroll
            for (int j = 0; j < 4; j++)
                wmma::store_matrix_sync(Sf + m * 68 + j * 16, acc[j], 68, wmma::mem_row_major);
        }
        __syncthreads();

        {
            int r = tid >> 1, hf = tid & 1;
            const float* srow = Sf + r * 68 + hf * 32;
            float ls = 0.f;
            __nv_bfloat16* prow = Ps + r * 72 + hf * 32;
            #pragma unroll
            for (int j = 0; j < 32; j++) {
                float p = __expf(srow[j]);
                ls += p;
                prow[j] = __float2bfloat16(p);
            }
            ls += __shfl_xor_sync(0xffffffffu, ls, 1);
            if (hf == 0) lrow[r] += ls;
        }
        __syncthreads();

        if (ch + 1 < 8) {
            prefetchKV(ch + 1, b ^ 1);
            CP_COMMIT;
        }

        {
            #pragma unroll
            for (int kk = 0; kk < 4; kk++) {
                wmma::fragment<wmma::matrix_a, 16, 16, 16, __nv_bfloat16, wmma::row_major> af[2];
                #pragma unroll
                for (int i = 0; i < 2; i++)
                    wmma::load_matrix_sync(af[i], Ps + (pm * 32 + i * 16) * 72 + kk * 16, 72);
                wmma::fragment<wmma::matrix_b, 16, 16, 16, __nv_bfloat16, wmma::row_major> bf[2];
                #pragma unroll
                for (int j = 0; j < 2; j++)
                    wmma::load_matrix_sync(bf[j], Vs + b * 4608 + (kk * 16) * 72 + pn * 32 + j * 16, 72);
                #pragma unroll
                for (int i = 0; i < 2; i++)
                    #pragma unroll
                    for (int j = 0; j < 2; j++)
                        wmma::mma_sync(acc_o[i][j], af[i], bf[j], acc_o[i][j]);
            }
        }
    }

    __syncthreads();
    #pragma unroll
    for (int i = 0; i < 2; i++)
        #pragma unroll
        for (int j = 0; j < 2; j++)
            wmma::store_matrix_sync(Sf + (pm * 32 + i * 16) * 68 + pn * 32 + j * 16,
                                    acc_o[i][j], 68, wmma::mem_row_major);
    __syncthreads();

    #pragma unroll
    for (int i = 0; i < 32; i++) {
        int idx = tid + i * 256;
        int r = idx & 127, d = idx >> 7;
        int cch = n * 256 + h * 64 + d;
        float v = Sf[r * 68 + d] / lrow[r];
        size_t gi = ((size_t)cch) * SV + s0 + r;
        float t = v + fmaf(A1[cch], attn[gi], D1[cch]);
        __nv_bfloat16 hi = __float2bfloat16(t);
        ghi[gi] = hi;
        glo[gi] = __float2bfloat16(t - __bfloat162float(hi));
    }
}

// =========================================================================
// host launch
// =========================================================================
extern "C" void kernel_launch(void* const* d_in, const int* in_sizes, int n_in,
                              void* d_out, int out_size) {
    const float* x      = (const float*)d_in[0];
    const float* qkv_w  = (const float*)d_in[1];
    const float* qkv_b  = (const float*)d_in[2];
    const float* norm_w = (const float*)d_in[3];
    const float* norm_b = (const float*)d_in[4];
    const float* anorm_w= (const float*)d_in[5];
    const float* anorm_b= (const float*)d_in[6];
    const float* dnorm_w= (const float*)d_in[7];
    const float* dnorm_b= (const float*)d_in[8];
    const float* q_w    = (const float*)d_in[9];
    const float* q_b    = (const float*)d_in[10];
    const float* kv_w   = (const float*)d_in[11];
    const float* kv_b   = (const float*)d_in[12];
    const float* proj_w = (const float*)d_in[13];
    const float* proj_b = (const float*)d_in[14];
    float* out = (float*)d_out;

    float *attn, *praw, *pnorm, *part, *part2, *aff, *qkvb2, *qb2;
    __nv_bfloat16 *xB, *qkvB, *attnB, *ghi, *glo, *pooledB, *q2T, *kvT;
    __nv_bfloat16 *Wqkv2B, *Wq2B, *WkvB, *WprojB;
    cudaGetSymbolAddress((void**)&attn,    g_attn);
    cudaGetSymbolAddress((void**)&praw,    g_praw);
    cudaGetSymbolAddress((void**)&pnorm,   g_pnorm);
    cudaGetSymbolAddress((void**)&xB,      g_xB);
    cudaGetSymbolAddress((void**)&qkvB,    g_qkvB);
    cudaGetSymbolAddress((void**)&attnB,   g_attnB);
    cudaGetSymbolAddress((void**)&ghi,     g_ghi);
    cudaGetSymbolAddress((void**)&glo,     g_glo);
    cudaGetSymbolAddress((void**)&pooledB, g_pooledB);
    cudaGetSymbolAddress((void**)&q2T,     g_q2T);
    cudaGetSymbolAddress((void**)&kvT,     g_kvT);
    cudaGetSymbolAddress((void**)&Wqkv2B,  g_Wqkv2B);
    cudaGetSymbolAddress((void**)&Wq2B,    g_Wq2B);
    cudaGetSymbolAddress((void**)&WkvB,    g_WkvB);
    cudaGetSymbolAddress((void**)&WprojB,  g_WprojB);
    cudaGetSymbolAddress((void**)&qkvb2,   g_qkvb2);
    cudaGetSymbolAddress((void**)&qb2,     g_qb2);
    cudaGetSymbolAddress((void**)&part,    g_part);
    cudaGetSymbolAddress((void**)&part2,   g_part2);
    cudaGetSymbolAddress((void**)&aff,     g_aff);

    static cudaStream_t s1 = nullptr;
    static cudaEvent_t ev0, evS1a, evA, evB, evA1, evKV;
    static bool init_done = false;
    if (!init_done) {
        cudaFuncSetAttribute(gattn_kernel, cudaFuncAttributeMaxDynamicSharedMemorySize, GA_SMEM);
        cudaFuncSetAttribute(wgemm3_kernel<0>, cudaFuncAttributeMaxDynamicSharedMemorySize, WG_SMEM);
        cudaFuncSetAttribute(wgemm3_kernel<1>, cudaFuncAttributeMaxDynamicSharedMemorySize, WG_SMEM);
        cudaFuncSetAttribute(wgemm3_kernel<2>, cudaFuncAttributeMaxDynamicSharedMemorySize, WG_SMEM);
        cudaStreamCreateWithFlags(&s1, cudaStreamNonBlocking);
        cudaEventCreateWithFlags(&ev0,  cudaEventDisableTiming);
        cudaEventCreateWithFlags(&evS1a, cudaEventDisableTiming);
        cudaEventCreateWithFlags(&evA,  cudaEventDisableTiming);
        cudaEventCreateWithFlags(&evB,  cudaEventDisableTiming);
        cudaEventCreateWithFlags(&evA1, cudaEventDisableTiming);
        cudaEventCreateWithFlags(&evKV, cudaEventDisableTiming);
        init_done = true;
    }

    float* A0 = aff;        float* D0 = aff + 512;
    float* A1 = aff + 1024; float* D1 = aff + 1536;
    float* A2 = aff + 2048; float* D2 = aff + 2560;

    // ---- fork: side = kv/proj weight convert; main = fused stats + xB ----
    cudaEventRecord(ev0, 0);
    cudaStreamWaitEvent(s1, ev0, 0);
    convert_weights_kernel<<<1280, 256, 0, s1>>>(kv_w, proj_w, WkvB, WprojB);
    cudaEventRecord(evS1a, s1);

    reduce1x_kernel<<<dim3(512, NB), 256>>>(x, 256L * SV / 4, part, xB);
    stats2affine_kernel<<<NB, 256>>>(part, 512, norm_w, norm_b, A0, D0, 1.f / (256.f * 32768.f));
    fold_kernel<<<dim3(768, NB), 256>>>(qkv_w, qkv_b, A0, D0, Wqkv2B, qkvb2, 768);

    cudaStreamWaitEvent(0, evS1a, 0);

    wgemm3_kernel<2><<<dim3(6, 256, NB), 256, WG_SMEM>>>(
        Wqkv2B, xB, xB, qkvb2, nullptr, qkvB, 768, (int)SV, 256, SCALE_INV,
        768L * 256, 768);

    local_attn_w_kernel<<<dim3(512, NH, NB), 128>>>(qkvB, x, attn, praw, part);

    cudaEventRecord(evA, 0);
    cudaStreamWaitEvent(s1, evA, 0);
    convert_plain_kernel<<<8192, 256, 0, s1>>>(attn, attnB);
    cudaEventRecord(evB, s1);

    stats2affine_kernel<<<NB, 256>>>(part, 2048, anorm_w, anorm_b, A1, D1, 1.f / (256.f * 32768.f));
    cudaEventRecord(evA1, 0);
    fold_kernel<<<dim3(256, NB), 256>>>(q_w, q_b, A1, D1, Wq2B, qb2, 256);

    cudaStreamWaitEvent(s1, evA1, 0);
    apply_pool_affine_kernel<<<256, 256, 0, s1>>>(praw, A1, D1, pnorm);
    reduce1_kernel<<<dim3(32, NB), 256, 0, s1>>>(pnorm, 256L * 512 / 4, part2);
    stats2affine_kernel<<<NB, 256, 0, s1>>>(part2, 32, dnorm_w, dnorm_b, A2, D2, 1.f / (256.f * 512.f));
    convert_pooled_kernel<<<256, 256, 0, s1>>>(pnorm, A2, D2, pooledB);
    wgemm3_kernel<1><<<dim3(4, 4, NB), 256, WG_SMEM, s1>>>(
        WkvB, pooledB, pooledB, kv_b, nullptr, kvT, 512, 512, 256, 1.f, 0, 0);
    cudaEventRecord(evKV, s1);

    cudaStreamWaitEvent(0, evB, 0);
    wgemm3_kernel<1><<<dim3(2, 256, NB), 256, WG_SMEM>>>(
        Wq2B, attnB, attnB, qb2, nullptr, q2T, 256, (int)SV, 256, SCALE_INV,
        256L * 256, 256);

    cudaStreamWaitEvent(0, evKV, 0);

    gattn_kernel<<<dim3(256, NH, NB), 256, GA_SMEM>>>(q2T, kvT, attn, A1, D1, ghi, glo);

    wgemm3_kernel<0><<<dim3(2, 256, NB), 256, WG_SMEM>>>(
        WprojB, ghi, glo, proj_b, out, nullptr, 256, (int)SV, 768, 1.f, 0, 0);
}

// round 15
// speedup vs baseline: 1.0353x; 1.0353x over previous
#include <cuda_runtime.h>
#include <cuda_bf16.h>
#include <mma.h>
#include <math.h>
#include <stdint.h>

using namespace nvcuda;

#define NB 2
#define CH 256
#define SV 32768L
#define NH 4
#define HD 64
#define SCALE_INV 0.0625f
#define EPS 1e-6f

__device__ __forceinline__ unsigned pack2(float a, float b) {
    __nv_bfloat162 t = __floats2bfloat162_rn(a, b);
    return *reinterpret_cast<unsigned*>(&t);
}

// ---------------- scratch ----------------
__device__ __align__(16) float g_attn   [NB * 256L * SV];
__device__ __align__(16) float g_praw   [NB * 256 * 512];
__device__ __align__(16) float g_pnorm  [NB * 256 * 512];
__device__ __align__(16) __nv_bfloat16 g_xB    [NB * 256L * SV];
__device__ __align__(16) __nv_bfloat16 g_qkvB  [NB * 768L * SV];
__device__ __align__(16) __nv_bfloat16 g_attnB [NB * 256L * SV];
__device__ __align__(16) __nv_bfloat16 g_ghi   [NB * 256L * SV];
__device__ __align__(16) __nv_bfloat16 g_glo   [NB * 256L * SV];
__device__ __align__(16) __nv_bfloat16 g_pooledB[NB * 256 * 512];
__device__ __align__(16) __nv_bfloat16 g_q2T   [NB * 4L * SV * 64];
__device__ __align__(16) __nv_bfloat16 g_kvT   [NB * 8L * 512 * 64];
__device__ __align__(16) __nv_bfloat16 g_Wqkv2B[NB * 768 * 256];
__device__ __align__(16) __nv_bfloat16 g_Wq2B  [NB * 256 * 256];
__device__ __align__(16) __nv_bfloat16 g_WkvB  [512 * 256];
__device__ __align__(16) __nv_bfloat16 g_WprojB[256 * 768];
__device__ float g_qkvb2[NB * 768];
__device__ float g_qb2  [NB * 256];
__device__ float g_part [NB * 2048 * 2];
__device__ float g_part2[NB * 64 * 2];
__device__ float g_aff  [6 * NB * 256];

// ---------------- cp.async ----------------
__device__ __forceinline__ void cp16(void* dst, const void* src) {
    unsigned d = (unsigned)__cvta_generic_to_shared(dst);
    asm volatile("cp.async.cg.shared.global [%0], [%1], 16;\n" :: "r"(d), "l"(src));
}
#define CP_COMMIT asm volatile("cp.async.commit_group;\n" ::: "memory")
#define CP_WAIT1  asm volatile("cp.async.wait_group 1;\n" ::: "memory")
#define CP_WAIT0  asm volatile("cp.async.wait_group 0;\n" ::: "memory")

// =========================================================================
// reductions / affine / conversions  (all n-free: per-batch via pointers)
// =========================================================================
__global__ void reduce1x_kernel(const float* __restrict__ buf, long per4,
                                float* __restrict__ part, __nv_bfloat16* __restrict__ outB) {
    const float4* p = reinterpret_cast<const float4*>(buf);
    uint2* ob = reinterpret_cast<uint2*>(outB);
    float s = 0.f, ss = 0.f;
    for (long i = (long)blockIdx.x * blockDim.x + threadIdx.x; i < per4;
         i += (long)gridDim.x * blockDim.x) {
        float4 v = p[i];
        s  += v.x + v.y + v.z + v.w;
        ss += v.x*v.x + v.y*v.y + v.z*v.z + v.w*v.w;
        uint2 r;
        r.x = pack2(v.x, v.y);
        r.y = pack2(v.z, v.w);
        ob[i] = r;
    }
    for (int o = 16; o; o >>= 1) {
        s  += __shfl_down_sync(0xffffffffu, s, o);
        ss += __shfl_down_sync(0xffffffffu, ss, o);
    }
    __shared__ float sh[64];
    int w = threadIdx.x >> 5;
    if ((threadIdx.x & 31) == 0) { sh[w] = s; sh[32 + w] = ss; }
    __syncthreads();
    if (threadIdx.x < 32) {
        int nw = blockDim.x >> 5;
        s  = (threadIdx.x < nw) ? sh[threadIdx.x]      : 0.f;
        ss = (threadIdx.x < nw) ? sh[32 + threadIdx.x] : 0.f;
        for (int o = 16; o; o >>= 1) {
            s  += __shfl_down_sync(0xffffffffu, s, o);
            ss += __shfl_down_sync(0xffffffffu, ss, o);
        }
        if (threadIdx.x == 0) {
            part[(size_t)blockIdx.x * 2 + 0] = s;
            part[(size_t)blockIdx.x * 2 + 1] = ss;
        }
    }
}

__global__ void reduce1_kernel(const float* __restrict__ buf, long per4, float* __restrict__ part) {
    const float4* p = reinterpret_cast<const float4*>(buf);
    float s = 0.f, ss = 0.f;
    for (long i = (long)blockIdx.x * blockDim.x + threadIdx.x; i < per4;
         i += (long)gridDim.x * blockDim.x) {
        float4 v = p[i];
        s  += v.x + v.y + v.z + v.w;
        ss += v.x*v.x + v.y*v.y + v.z*v.z + v.w*v.w;
    }
    for (int o = 16; o; o >>= 1) {
        s  += __shfl_down_sync(0xffffffffu, s, o);
        ss += __shfl_down_sync(0xffffffffu, ss, o);
    }
    __shared__ float sh[64];
    int w = threadIdx.x >> 5;
    if ((threadIdx.x & 31) == 0) { sh[w] = s; sh[32 + w] = ss; }
    __syncthreads();
    if (threadIdx.x < 32) {
        int nw = blockDim.x >> 5;
        s  = (threadIdx.x < nw) ? sh[threadIdx.x]      : 0.f;
        ss = (threadIdx.x < nw) ? sh[32 + threadIdx.x] : 0.f;
        for (int o = 16; o; o >>= 1) {
            s  += __shfl_down_sync(0xffffffffu, s, o);
            ss += __shfl_down_sync(0xffffffffu, ss, o);
        }
        if (threadIdx.x == 0) {
            part[(size_t)blockIdx.x * 2 + 0] = s;
            part[(size_t)blockIdx.x * 2 + 1] = ss;
        }
    }
}

__global__ void stats2affine_kernel(const float* __restrict__ part, int nb,
                                    const float* __restrict__ w, const float* __restrict__ b,
                                    float* __restrict__ a, float* __restrict__ d,
                                    float inv_cnt) {
    int tid = threadIdx.x;
    float s = 0.f, ss = 0.f;
    for (int i = tid; i < nb; i += 256) {
        s  += part[(size_t)i * 2 + 0];
        ss += part[(size_t)i * 2 + 1];
    }
    for (int o = 16; o; o >>= 1) {
        s  += __shfl_down_sync(0xffffffffu, s, o);
        ss += __shfl_down_sync(0xffffffffu, ss, o);
    }
    __shared__ float sh[16];
    __shared__ float sm_mean, sm_rstd;
    int wp = tid >> 5;
    if ((tid & 31) == 0) { sh[wp] = s; sh[8 + wp] = ss; }
    __syncthreads();
    if (tid < 32) {
        s  = (tid < 8) ? sh[tid]     : 0.f;
        ss = (tid < 8) ? sh[8 + tid] : 0.f;
        for (int o = 4; o; o >>= 1) {
            s  += __shfl_down_sync(0xffffffffu, s, o);
            ss += __shfl_down_sync(0xffffffffu, ss, o);
        }
        if (tid == 0) {
            float mean = s * inv_cnt;
            float var  = ss * inv_cnt - mean * mean;
            sm_mean = mean;
            sm_rstd = rsqrtf(var + EPS);
        }
    }
    __syncthreads();
    float mean = sm_mean, rstd = sm_rstd;
    a[tid] = w[tid] * rstd;
    d[tid] = b[tid] - mean * rstd * w[tid];
}

__global__ void convert_plain_kernel(const float* __restrict__ x, __nv_bfloat16* __restrict__ out) {
    size_t i8 = (size_t)blockIdx.x * blockDim.x + threadIdx.x;
    const float4* p = reinterpret_cast<const float4*>(x) + i8 * 2;
    float4 v0 = p[0], v1 = p[1];
    uint4 u;
    u.x = pack2(v0.x, v0.y);
    u.y = pack2(v0.z, v0.w);
    u.z = pack2(v1.x, v1.y);
    u.w = pack2(v1.z, v1.w);
    reinterpret_cast<uint4*>(out)[i8] = u;
}

__global__ void fold_kernel(const float* __restrict__ W, const float* __restrict__ bsrc,
                            const float* __restrict__ A, const float* __restrict__ D,
                            __nv_bfloat16* __restrict__ W2, float* __restrict__ b2) {
    int m = blockIdx.x, tid = threadIdx.x;
    float w = W[(size_t)m * 256 + tid];
    float aa = A[tid], dd = D[tid];
    W2[(size_t)m * 256 + tid] = __float2bfloat16(w * aa);
    float pr = w * dd;
    for (int o = 16; o; o >>= 1) pr += __shfl_down_sync(0xffffffffu, pr, o);
    __shared__ float sh[8];
    if ((tid & 31) == 0) sh[tid >> 5] = pr;
    __syncthreads();
    if (tid == 0) {
        float t = 0.f;
        #pragma unroll
        for (int i = 0; i < 8; i++) t += sh[i];
        b2[m] = bsrc[m] + t;
    }
}

__global__ void apply_pool_affine_kernel(const float* __restrict__ praw,
                                         const float* __restrict__ a, const float* __restrict__ d,
                                         float* __restrict__ pnorm) {
    size_t i4 = (size_t)blockIdx.x * blockDim.x + threadIdx.x;  // 32768 float4 per batch
    int c = (int)(i4 >> 7);
    float aa = a[c], dd = d[c];
    float4 v = reinterpret_cast<const float4*>(praw)[i4];
    v.x = fmaf(aa, v.x, dd); v.y = fmaf(aa, v.y, dd);
    v.z = fmaf(aa, v.z, dd); v.w = fmaf(aa, v.w, dd);
    reinterpret_cast<float4*>(pnorm)[i4] = v;
}

__global__ void convert_pooled_kernel(const float* __restrict__ pooled,
                                      const float* __restrict__ a, const float* __restrict__ d,
                                      __nv_bfloat16* __restrict__ out) {
    size_t i4 = (size_t)blockIdx.x * blockDim.x + threadIdx.x;
    int c = (int)(i4 >> 7);
    float aa = a[c], dd = d[c];
    float4 v = reinterpret_cast<const float4*>(pooled)[i4];
    uint2 r;
    r.x = pack2(fmaf(aa, v.x, dd), fmaf(aa, v.y, dd));
    r.y = pack2(fmaf(aa, v.z, dd), fmaf(aa, v.w, dd));
    reinterpret_cast<uint2*>(out)[i4] = r;
}

__global__ void convert_weights_kernel(
    const float* __restrict__ kv_w, const float* __restrict__ proj_w,
    __nv_bfloat16* __restrict__ Wkv, __nv_bfloat16* __restrict__ Wproj) {
    int idx = blockIdx.x * blockDim.x + threadIdx.x;
    const int T1 = 512 * 256, T2 = T1 + 256 * 768;
    if (idx < T1) {
        Wkv[idx] = __float2bfloat16(kv_w[idx]);
    } else if (idx < T2) {
        int j = idx - T1;
        int m = j / 768, k = j % 768;
        float v = proj_w[m * 256 + (k & 255)];
        __nv_bfloat16 hi = __float2bfloat16(v);
        if (k >= 256 && k < 512) hi = __float2bfloat16(v - __bfloat162float(hi));
        Wproj[j] = hi;
    }
}

// =========================================================================
// wgemm3: BM=128, BN=128, BK=64, 3-stage cp.async, 256 threads, 2 blocks/SM.
// Per-batch launch: z dims gone, pointers pre-offset by host.
// =========================================================================
#define WG_A_STG 9216
#define WG_B_STG 8704
#define WG_SMEM (3 * (WG_A_STG + WG_B_STG) * 2)

template<int MODE>
__global__ void __launch_bounds__(256, 2) wgemm3_kernel(
    const __nv_bfloat16* __restrict__ A,
    const __nv_bfloat16* __restrict__ B0, const __nv_bfloat16* __restrict__ B1,
    const float* __restrict__ bias,
    float* __restrict__ outF, __nv_bfloat16* __restrict__ outB,
    int M, int S, int KT, float qScale) {
    extern __shared__ __align__(16) char dsm[];
    __nv_bfloat16* As = (__nv_bfloat16*)dsm;
    __nv_bfloat16* Bs = (__nv_bfloat16*)(dsm + 3 * WG_A_STG * 2);
    float* Cs = (float*)dsm;

    int tid = threadIdx.x, warp = tid >> 5;
    int wm = warp >> 2, wn = warp & 3;
    int m0 = blockIdx.x * 128;
    int s0 = blockIdx.y * 128;

    wmma::fragment<wmma::accumulator, 16, 16, 16, float> acc[4][2];
    #pragma unroll
    for (int i = 0; i < 4; i++)
        #pragma unroll
        for (int j = 0; j < 2; j++) wmma::fill_fragment(acc[i][j], 0.f);

    const int NIT = KT >> 6;

    auto prefetch = [&](int it, int buf) {
        int ktL = it * 64;
        #pragma unroll
        for (int i = 0; i < 4; i++) {
            int c = tid + i * 256;
            int r = c >> 3, q = (c & 7) * 8;
            cp16(As + buf * WG_A_STG + r * 72 + q,
                 A + (size_t)(m0 + r) * KT + ktL + q);
        }
        const __nv_bfloat16* Bp = (ktL < 512) ? B0 : B1;
        int krow = ktL & 255;
        #pragma unroll
        for (int i = 0; i < 4; i++) {
            int c = tid + i * 256;
            int r = c >> 4, q = (c & 15) * 8;
            cp16(Bs + buf * WG_B_STG + r * 136 + q,
                 Bp + (size_t)(krow + r) * S + s0 + q);
        }
    };

    prefetch(0, 0); CP_COMMIT;
    if (NIT > 1) { prefetch(1, 1); CP_COMMIT; }

    int buf = 0;
    for (int it = 0; it < NIT; it++) {
        if (it + 1 < NIT) CP_WAIT1; else CP_WAIT0;
        __syncthreads();
        #pragma unroll
        for (int ks = 0; ks < 4; ks++) {
            wmma::fragment<wmma::matrix_a, 16, 16, 16, __nv_bfloat16, wmma::row_major> af[4];
            #pragma unroll
            for (int i = 0; i < 4; i++)
                wmma::load_matrix_sync(af[i], As + buf * WG_A_STG + (wm * 64 + i * 16) * 72 + ks * 16, 72);
            wmma::fragment<wmma::matrix_b, 16, 16, 16, __nv_bfloat16, wmma::row_major> bf[2];
            #pragma unroll
            for (int j = 0; j < 2; j++)
                wmma::load_matrix_sync(bf[j], Bs + buf * WG_B_STG + (ks * 16) * 136 + wn * 32 + j * 16, 136);
            #pragma unroll
            for (int i = 0; i < 4; i++)
                #pragma unroll
                for (int j = 0; j < 2; j++)
                    wmma::mma_sync(acc[i][j], af[i], bf[j], acc[i][j]);
        }
        if (it + 2 < NIT) {
            prefetch(it + 2, (buf + 2) % 3);
            CP_COMMIT;
        }
        buf = (buf + 1) % 3;
    }

    __syncthreads();

    if (MODE == 0) {
        #pragma unroll
        for (int i = 0; i < 4; i++)
            #pragma unroll
            for (int j = 0; j < 2; j++)
                wmma::store_matrix_sync(Cs + (wm * 64 + i * 16) * 132 + wn * 32 + j * 16,
                                        acc[i][j], 132, wmma::mem_row_major);
        __syncthreads();
        float* Ob = outF + (size_t)m0 * S;
        #pragma unroll
        for (int it = 0; it < 16; it++) {
            int idx = tid + it * 256;
            int r = idx >> 5, c4 = idx & 31;
            float bv = bias[m0 + r];
            float4 v = *reinterpret_cast<const float4*>(&Cs[r * 132 + c4 * 4]);
            v.x += bv; v.y += bv; v.z += bv; v.w += bv;
            *reinterpret_cast<float4*>(&Ob[(size_t)r * S + s0 + c4 * 4]) = v;
        }
    } else {
        #pragma unroll
        for (int i = 0; i < 4; i++)
            #pragma unroll
            for (int j = 0; j < 2; j++)
                wmma::store_matrix_sync(Cs + (wn * 32 + j * 16) * 136 + wm * 64 + i * 16,
                                        acc[i][j], 136, wmma::mem_col_major);
        __syncthreads();

        int dg = tid & 15;
        int gmb = m0 + dg * 8;
        float bias8[8];
        #pragma unroll
        for (int e = 0; e < 8; e++) bias8[e] = bias[gmb + e];

        float sc;
        int db = gmb & 63;
        __nv_bfloat16* hbase;
        if (MODE == 1) {
            int hb = gmb >> 6;
            sc = qScale;
            hbase = outB + ((size_t)hb * S + s0) * 64 + db;
        } else {
            int sel = gmb >> 8, head = (gmb >> 6) & 3;
            sc = (sel == 0) ? qScale : 1.f;
            hbase = outB + (((size_t)sel * 4 + head) * 512) * 4096 + db;
        }

        #pragma unroll
        for (int it = 0; it < 8; it++) {
            int sl = it * 16 + (tid >> 4);
            float4 lo = *reinterpret_cast<const float4*>(&Cs[sl * 136 + dg * 8]);
            float4 hi = *reinterpret_cast<const float4*>(&Cs[sl * 136 + dg * 8 + 4]);
            float f[8] = {lo.x, lo.y, lo.z, lo.w, hi.x, hi.y, hi.z, hi.w};
            #pragma unroll
            for (int e = 0; e < 8; e++) f[e] = (f[e] + bias8[e]) * sc;
            uint4 u;
            u.x = pack2(f[0], f[1]);
            u.y = pack2(f[2], f[3]);
            u.z = pack2(f[4], f[5]);
            u.w = pack2(f[6], f[7]);
            size_t off;
            if (MODE == 1) {
                off = (size_t)sl * 64;
            } else {
                int s = s0 + sl;
                int d5 = s & 31, w5 = (s >> 5) & 31, h5 = s >> 10;
                int window = ((h5 >> 2) * 8 + (w5 >> 2)) * 8 + (d5 >> 2);
                int token  = (((h5 & 3) * 4 + (w5 & 3)) * 4 + (d5 & 3));
                off = (size_t)window * 4096 + token * 64;
            }
            *reinterpret_cast<uint4*>(hbase + off) = u;
        }
    }
}

// =========================================================================
// Local windowed attention — per-batch pointers
// =========================================================================
__global__ void __launch_bounds__(128) local_attn_w_kernel(
    const __nv_bfloat16* __restrict__ qkvB, const float* __restrict__ x,
    float* __restrict__ attn, float* __restrict__ praw, float* __restrict__ part) {
    __shared__ __align__(16) __nv_bfloat16 QP[64 * 72];
    __shared__ __align__(16) __nv_bfloat16 Ks[64 * 72];
    __shared__ __align__(16) __nv_bfloat16 Vs[64 * 72];
    __shared__ __align__(16) float Sf[64 * 68];
    __shared__ float linv[64];
    __shared__ float rs[4], rss[4];

    int w = blockIdx.x, head = blockIdx.y;
    int tid = threadIdx.x, warp = tid >> 5;

    size_t base = ((size_t)head * 512 + w) * 4096;
    size_t step = (size_t)4 * 512 * 4096;
    const uint4* Qg = (const uint4*)(qkvB + base);
    const uint4* Kg = (const uint4*)(qkvB + base + step);
    const uint4* Vg = (const uint4*)(qkvB + base + 2 * step);

    #pragma unroll
    for (int i = 0; i < 4; i++) {
        int c = tid + i * 128;
        int r = c >> 3, q = c & 7;
        ((uint4*)(QP + r * 72))[q] = Qg[c];
        ((uint4*)(Ks + r * 72))[q] = Kg[c];
        ((uint4*)(Vs + r * 72))[q] = Vg[c];
    }
    __syncthreads();

    {
        int m = warp * 16;
        wmma::fragment<wmma::accumulator, 16, 16, 16, float> acc[4];
        #pragma unroll
        for (int j = 0; j < 4; j++) wmma::fill_fragment(acc[j], 0.f);
        #pragma unroll
        for (int kd = 0; kd < 4; kd++) {
            wmma::fragment<wmma::matrix_a, 16, 16, 16, __nv_bfloat16, wmma::row_major> af;
            wmma::load_matrix_sync(af, QP + m * 72 + kd * 16, 72);
            #pragma unroll
            for (int j = 0; j < 4; j++) {
                wmma::fragment<wmma::matrix_b, 16, 16, 16, __nv_bfloat16, wmma::col_major> bf;
                wmma::load_matrix_sync(bf, Ks + (j * 16) * 72 + kd * 16, 72);
                wmma::mma_sync(acc[j], af, bf, acc[j]);
            }
        }
        #pragma unroll
        for (int j = 0; j < 4; j++)
            wmma::store_matrix_sync(Sf + m * 68 + j * 16, acc[j], 68, wmma::mem_row_major);
    }
    __syncthreads();

    {
        int r = tid >> 1, hf = tid & 1;
        const float* srow = Sf + r * 68 + hf * 32;
        float ls = 0.f;
        __nv_bfloat16* prow = QP + r * 72 + hf * 32;
        #pragma unroll
        for (int j = 0; j < 32; j++) {
            float p = __expf(srow[j]);
            ls += p;
            prow[j] = __float2bfloat16(p);
        }
        ls += __shfl_xor_sync(0xffffffffu, ls, 1);
        if (hf == 0) linv[r] = 1.f / ls;
    }
    __syncthreads();

    {
        int m = warp * 16;
        wmma::fragment<wmma::accumulator, 16, 16, 16, float> acc[4];
        #pragma unroll
        for (int j = 0; j < 4; j++) wmma::fill_fragment(acc[j], 0.f);
        #pragma unroll
        for (int kk = 0; kk < 4; kk++) {
            wmma::fragment<wmma::matrix_a, 16, 16, 16, __nv_bfloat16, wmma::row_major> af;
            wmma::load_matrix_sync(af, QP + m * 72 + kk * 16, 72);
            #pragma unroll
            for (int j = 0; j < 4; j++) {
                wmma::fragment<wmma::matrix_b, 16, 16, 16, __nv_bfloat16, wmma::row_major> bf;
                wmma::load_matrix_sync(bf, Vs + (kk * 16) * 72 + j * 16, 72);
                wmma::mma_sync(acc[j], af, bf, acc[j]);
            }
        }
        #pragma unroll
        for (int j = 0; j < 4; j++)
            wmma::store_matrix_sync(Sf + m * 68 + j * 16, acc[j], 68, wmma::mem_row_major);
    }
    __syncthreads();

    int wh = w >> 6, ww = (w >> 3) & 7, wd = w & 7;
    int base_s = wh * 4096 + ww * 128 + wd * 4;
    int chb = head * 64;
    float s_acc = 0.f, ss_acc = 0.f;
    #pragma unroll
    for (int it = 0; it < 8; it++) {
        int idx = tid + it * 128;
        int d = idx >> 4, tg = idx & 15;
        int i_ = tg >> 2, j_ = tg & 3;
        int s = base_s + i_ * 1024 + j_ * 32;
        int t0 = tg * 4;
        size_t g = ((size_t)(chb + d)) * SV + s;
        float4 xv = *reinterpret_cast<const float4*>(x + g);
        float4 ov;
        ov.x = fmaf(Sf[(t0 + 0) * 68 + d], linv[t0 + 0], xv.x);
        ov.y = fmaf(Sf[(t0 + 1) * 68 + d], linv[t0 + 1], xv.y);
        ov.z = fmaf(Sf[(t0 + 2) * 68 + d], linv[t0 + 2], xv.z);
        ov.w = fmaf(Sf[(t0 + 3) * 68 + d], linv[t0 + 3], xv.w);
        *reinterpret_cast<float4*>(attn + g) = ov;
        float ps = ov.x + ov.y + ov.z + ov.w;
        s_acc  += ps;
        ss_acc += ov.x*ov.x + ov.y*ov.y + ov.z*ov.z + ov.w*ov.w;
        #pragma unroll
        for (int o = 8; o; o >>= 1) ps += __shfl_down_sync(0xffffffffu, ps, o);
        if ((tid & 15) == 0)
            praw[((size_t)(chb + d)) * 512 + w] = ps * (1.f / 64.f);
    }
    #pragma unroll
    for (int o = 16; o; o >>= 1) {
        s_acc  += __shfl_down_sync(0xffffffffu, s_acc, o);
        ss_acc += __shfl_down_sync(0xffffffffu, ss_acc, o);
    }
    if ((tid & 31) == 0) { rs[warp] = s_acc; rss[warp] = ss_acc; }
    __syncthreads();
    if (tid == 0) {
        size_t pi = (size_t)head * 512 + w;
        part[pi * 2 + 0] = rs[0] + rs[1] + rs[2] + rs[3];
        part[pi * 2 + 1] = rss[0] + rss[1] + rss[2] + rss[3];
    }
}

// =========================================================================
// Global attention — per-batch pointers
// =========================================================================
#define GA_SMEM 109056

__global__ void __launch_bounds__(256, 2) gattn_kernel(
    const __nv_bfloat16* __restrict__ q2T, const __nv_bfloat16* __restrict__ kvT,
    const float* __restrict__ attn,
    const float* __restrict__ A1, const float* __restrict__ D1,
    __nv_bfloat16* __restrict__ ghi, __nv_bfloat16* __restrict__ glo) {
    extern __shared__ __align__(16) char sm[];
    __nv_bfloat16* Qs = (__nv_bfloat16*)sm;
    __nv_bfloat16* Ks = Qs + 128 * 72;
    __nv_bfloat16* Vs = Ks + 2 * 64 * 72;
    __nv_bfloat16* Ps = Vs + 2 * 64 * 72;
    float* Sf   = (float*)(Ps + 128 * 72);
    float* lrow = Sf + 128 * 68;

    int tid = threadIdx.x, warp = tid >> 5;
    int h = blockIdx.y;
    int s0 = blockIdx.x * 128;

    const uint4* Qg = (const uint4*)(q2T + ((size_t)h * SV + s0) * 64);
    const __nv_bfloat16* Kg = kvT + ((size_t)h * 512) * 64;
    const __nv_bfloat16* Vg = kvT + ((size_t)(4 + h) * 512) * 64;

    auto prefetchKV = [&](int ch, int b) {
        #pragma unroll
        for (int i = 0; i < 2; i++) {
            int idx = tid + i * 256;
            int r = idx >> 3, c = (idx & 7) * 8;
            cp16(Ks + b * 4608 + r * 72 + c, Kg + (size_t)(ch * 64 + r) * 64 + c);
            cp16(Vs + b * 4608 + r * 72 + c, Vg + (size_t)(ch * 64 + r) * 64 + c);
        }
    };

    prefetchKV(0, 0); CP_COMMIT;

    #pragma unroll
    for (int i = 0; i < 4; i++) {
        int idx = tid + i * 256;
        int r = idx >> 3, c = idx & 7;
        ((uint4*)(Qs + r * 72))[c] = Qg[r * 8 + c];
    }
    if (tid < 128) lrow[tid] = 0.f;

    int pm = warp >> 1, pn = warp & 1;
    wmma::fragment<wmma::accumulator, 16, 16, 16, float> acc_o[2][2];
    #pragma unroll
    for (int i = 0; i < 2; i++)
        #pragma unroll
        for (int j = 0; j < 2; j++) wmma::fill_fragment(acc_o[i][j], 0.f);

    for (int ch = 0; ch < 8; ch++) {
        int b = ch & 1;
        CP_WAIT0;
        __syncthreads();

        {
            int m = warp * 16;
            wmma::fragment<wmma::accumulator, 16, 16, 16, float> acc[4];
            #pragma unroll
            for (int j = 0; j < 4; j++) wmma::fill_fragment(acc[j], 0.f);
            #pragma unroll
            for (int kd = 0; kd < 4; kd++) {
                wmma::fragment<wmma::matrix_a, 16, 16, 16, __nv_bfloat16, wmma::row_major> af;
                wmma::load_matrix_sync(af, Qs + m * 72 + kd * 16, 72);
                #pragma unroll
                for (int j = 0; j < 4; j++) {
                    wmma::fragment<wmma::matrix_b, 16, 16, 16, __nv_bfloat16, wmma::col_major> bf;
                    wmma::load_matrix_sync(bf, Ks + b * 4608 + (j * 16) * 72 + kd * 16, 72);
                    wmma::mma_sync(acc[j], af, bf, acc[j]);
                }
            }
            #pragma unroll
            for (int j = 0; j < 4; j++)
                wmma::store_matrix_sync(Sf + m * 68 + j * 16, acc[j], 68, wmma::mem_row_major);
        }
        __syncthreads();

        {
            int r = tid >> 1, hf = tid & 1;
            const float* srow = Sf + r * 68 + hf * 32;
            float ls = 0.f;
            __nv_bfloat16* prow = Ps + r * 72 + hf * 32;
            #pragma unroll
            for (int j = 0; j < 32; j++) {
                float p = __expf(srow[j]);
                ls += p;
                prow[j] = __float2bfloat16(p);
            }
            ls += __shfl_xor_sync(0xffffffffu, ls, 1);
            if (hf == 0) lrow[r] += ls;
        }
        __syncthreads();

        if (ch + 1 < 8) {
            prefetchKV(ch + 1, b ^ 1);
            CP_COMMIT;
        }

        {
            #pragma unroll
            for (int kk = 0; kk < 4; kk++) {
                wmma::fragment<wmma::matrix_a, 16, 16, 16, __nv_bfloat16, wmma::row_major> af[2];
                #pragma unroll
                for (int i = 0; i < 2; i++)
                    wmma::load_matrix_sync(af[i], Ps + (pm * 32 + i * 16) * 72 + kk * 16, 72);
                wmma::fragment<wmma::matrix_b, 16, 16, 16, __nv_bfloat16, wmma::row_major> bf[2];
                #pragma unroll
                for (int j = 0; j < 2; j++)
                    wmma::load_matrix_sync(bf[j], Vs + b * 4608 + (kk * 16) * 72 + pn * 32 + j * 16, 72);
                #pragma unroll
                for (int i = 0; i < 2; i++)
                    #pragma unroll
                    for (int j = 0; j < 2; j++)
                        wmma::mma_sync(acc_o[i][j], af[i], bf[j], acc_o[i][j]);
            }
        }
    }

    __syncthreads();
    #pragma unroll
    for (int i = 0; i < 2; i++)
        #pragma unroll
        for (int j = 0; j < 2; j++)
            wmma::store_matrix_sync(Sf + (pm * 32 + i * 16) * 68 + pn * 32 + j * 16,
                                    acc_o[i][j], 68, wmma::mem_row_major);
    __syncthreads();

    #pragma unroll
    for (int i = 0; i < 32; i++) {
        int idx = tid + i * 256;
        int r = idx & 127, d = idx >> 7;
        int cch = h * 64 + d;
        float v = Sf[r * 68 + d] / lrow[r];
        size_t gi = ((size_t)cch) * SV + s0 + r;
        float t = v + fmaf(A1[cch], attn[gi], D1[cch]);
        __nv_bfloat16 hi = __float2bfloat16(t);
        ghi[gi] = hi;
        glo[gi] = __float2bfloat16(t - __bfloat162float(hi));
    }
}

// =========================================================================
// host launch — one stream per batch, full pipeline overlap
// =========================================================================
extern "C" void kernel_launch(void* const* d_in, const int* in_sizes, int n_in,
                              void* d_out, int out_size) {
    const float* x      = (const float*)d_in[0];
    const float* qkv_w  = (const float*)d_in[1];
    const float* qkv_b  = (const float*)d_in[2];
    const float* norm_w = (const float*)d_in[3];
    const float* norm_b = (const float*)d_in[4];
    const float* anorm_w= (const float*)d_in[5];
    const float* anorm_b= (const float*)d_in[6];
    const float* dnorm_w= (const float*)d_in[7];
    const float* dnorm_b= (const float*)d_in[8];
    const float* q_w    = (const float*)d_in[9];
    const float* q_b    = (const float*)d_in[10];
    const float* kv_w   = (const float*)d_in[11];
    const float* kv_b   = (const float*)d_in[12];
    const float* proj_w = (const float*)d_in[13];
    const float* proj_b = (const float*)d_in[14];
    float* out = (float*)d_out;

    float *attn, *praw, *pnorm, *part, *part2, *aff, *qkvb2, *qb2;
    __nv_bfloat16 *xB, *qkvB, *attnB, *ghi, *glo, *pooledB, *q2T, *kvT;
    __nv_bfloat16 *Wqkv2B, *Wq2B, *WkvB, *WprojB;
    cudaGetSymbolAddress((void**)&attn,    g_attn);
    cudaGetSymbolAddress((void**)&praw,    g_praw);
    cudaGetSymbolAddress((void**)&pnorm,   g_pnorm);
    cudaGetSymbolAddress((void**)&xB,      g_xB);
    cudaGetSymbolAddress((void**)&qkvB,    g_qkvB);
    cudaGetSymbolAddress((void**)&attnB,   g_attnB);
    cudaGetSymbolAddress((void**)&ghi,     g_ghi);
    cudaGetSymbolAddress((void**)&glo,     g_glo);
    cudaGetSymbolAddress((void**)&pooledB, g_pooledB);
    cudaGetSymbolAddress((void**)&q2T,     g_q2T);
    cudaGetSymbolAddress((void**)&kvT,     g_kvT);
    cudaGetSymbolAddress((void**)&Wqkv2B,  g_Wqkv2B);
    cudaGetSymbolAddress((void**)&Wq2B,    g_Wq2B);
    cudaGetSymbolAddress((void**)&WkvB,    g_WkvB);
    cudaGetSymbolAddress((void**)&WprojB,  g_WprojB);
    cudaGetSymbolAddress((void**)&qkvb2,   g_qkvb2);
    cudaGetSymbolAddress((void**)&qb2,     g_qb2);
    cudaGetSymbolAddress((void**)&part,    g_part);
    cudaGetSymbolAddress((void**)&part2,   g_part2);
    cudaGetSymbolAddress((void**)&aff,     g_aff);

    static cudaStream_t s1 = nullptr;
    static cudaEvent_t ev0, evW, evDone;
    static bool init_done = false;
    if (!init_done) {
        cudaFuncSetAttribute(gattn_kernel, cudaFuncAttributeMaxDynamicSharedMemorySize, GA_SMEM);
        cudaFuncSetAttribute(wgemm3_kernel<0>, cudaFuncAttributeMaxDynamicSharedMemorySize, WG_SMEM);
        cudaFuncSetAttribute(wgemm3_kernel<1>, cudaFuncAttributeMaxDynamicSharedMemorySize, WG_SMEM);
        cudaFuncSetAttribute(wgemm3_kernel<2>, cudaFuncAttributeMaxDynamicSharedMemorySize, WG_SMEM);
        cudaStreamCreateWithFlags(&s1, cudaStreamNonBlocking);
        cudaEventCreateWithFlags(&ev0,    cudaEventDisableTiming);
        cudaEventCreateWithFlags(&evW,    cudaEventDisableTiming);
        cudaEventCreateWithFlags(&evDone, cudaEventDisableTiming);
        init_done = true;
    }

    // fork side stream; weights convert once on s1
    cudaEventRecord(ev0, 0);
    cudaStreamWaitEvent(s1, ev0, 0);
    convert_weights_kernel<<<1280, 256, 0, s1>>>(kv_w, proj_w, WkvB, WprojB);
    cudaEventRecord(evW, s1);

    // per-batch pipelines: n=0 on default stream, n=1 on s1
    for (int n = 0; n < NB; n++) {
        cudaStream_t st = (n == 0) ? (cudaStream_t)0 : s1;
        const float* x_n       = x      + (size_t)n * 256 * SV;
        float* attn_n          = attn   + (size_t)n * 256 * SV;
        float* praw_n          = praw   + (size_t)n * 256 * 512;
        float* pnorm_n         = pnorm  + (size_t)n * 256 * 512;
        __nv_bfloat16* xB_n    = xB     + (size_t)n * 256 * SV;
        __nv_bfloat16* qkvB_n  = qkvB   + (size_t)n * 768 * SV;
        __nv_bfloat16* attnB_n = attnB  + (size_t)n * 256 * SV;
        __nv_bfloat16* ghi_n   = ghi    + (size_t)n * 256 * SV;
        __nv_bfloat16* glo_n   = glo    + (size_t)n * 256 * SV;
        __nv_bfloat16* pooledB_n = pooledB + (size_t)n * 256 * 512;
        __nv_bfloat16* q2T_n   = q2T    + (size_t)n * 4 * SV * 64;
        __nv_bfloat16* kvT_n   = kvT    + (size_t)n * 8 * 512 * 64;
        __nv_bfloat16* Wqkv2_n = Wqkv2B + (size_t)n * 768 * 256;
        __nv_bfloat16* Wq2_n   = Wq2B   + (size_t)n * 256 * 256;
        float* qkvb2_n = qkvb2 + n * 768;
        float* qb2_n   = qb2   + n * 256;
        float* part_n  = part  + (size_t)n * 2048 * 2;
        float* part2_n = part2 + (size_t)n * 64 * 2;
        float* A0n = aff + n * 256;          float* D0n = aff + 512 + n * 256;
        float* A1n = aff + 1024 + n * 256;   float* D1n = aff + 1536 + n * 256;
        float* A2n = aff + 2048 + n * 256;   float* D2n = aff + 2560 + n * 256;
        float* out_n = out + (size_t)n * 256 * SV;

        reduce1x_kernel<<<512, 256, 0, st>>>(x_n, 256L * SV / 4, part_n, xB_n);
        stats2affine_kernel<<<1, 256, 0, st>>>(part_n, 512, norm_w, norm_b, A0n, D0n,
                                               1.f / (256.f * 32768.f));
        fold_kernel<<<768, 256, 0, st>>>(qkv_w, qkv_b, A0n, D0n, Wqkv2_n, qkvb2_n);

        wgemm3_kernel<2><<<dim3(6, 256), 256, WG_SMEM, st>>>(
            Wqkv2_n, xB_n, xB_n, qkvb2_n, nullptr, qkvB_n, 768, (int)SV, 256, SCALE_INV);

        local_attn_w_kernel<<<dim3(512, NH), 128, 0, st>>>(qkvB_n, x_n, attn_n, praw_n, part_n);

        stats2affine_kernel<<<1, 256, 0, st>>>(part_n, 2048, anorm_w, anorm_b, A1n, D1n,
                                               1.f / (256.f * 32768.f));
        fold_kernel<<<256, 256, 0, st>>>(q_w, q_b, A1n, D1n, Wq2_n, qb2_n);

        convert_plain_kernel<<<4096, 256, 0, st>>>(attn_n, attnB_n);

        apply_pool_affine_kernel<<<128, 256, 0, st>>>(praw_n, A1n, D1n, pnorm_n);
        reduce1_kernel<<<32, 256, 0, st>>>(pnorm_n, 256L * 512 / 4, part2_n);
        stats2affine_kernel<<<1, 256, 0, st>>>(part2_n, 32, dnorm_w, dnorm_b, A2n, D2n,
                                               1.f / (256.f * 512.f));
        convert_pooled_kernel<<<128, 256, 0, st>>>(pnorm_n, A2n, D2n, pooledB_n);

        if (n == 0) cudaStreamWaitEvent(st, evW, 0);   // batch0 needs WkvB/WprojB
        wgemm3_kernel<1><<<dim3(4, 4), 256, WG_SMEM, st>>>(
            WkvB, pooledB_n, pooledB_n, kv_b, nullptr, kvT_n, 512, 512, 256, 1.f);

        wgemm3_kernel<1><<<dim3(2, 256), 256, WG_SMEM, st>>>(
            Wq2_n, attnB_n, attnB_n, qb2_n, nullptr, q2T_n, 256, (int)SV, 256, SCALE_INV);

        gattn_kernel<<<dim3(256, NH), 256, GA_SMEM, st>>>(
            q2T_n, kvT_n, attn_n, A1n, D1n, ghi_n, glo_n);

        wgemm3_kernel<0><<<dim3(2, 256), 256, WG_SMEM, st>>>(
            WprojB, ghi_n, glo_n, proj_b, out_n, nullptr, 256, (int)SV, 768, 1.f);
    }

    // join batch1 into default stream
    cudaEventRecord(evDone, s1);
    cudaStreamWaitEvent(0, evDone, 0);
}

// round 16
// speedup vs baseline: 1.0596x; 1.0235x over previous
#include <cuda_runtime.h>
#include <cuda_bf16.h>
#include <mma.h>
#include <math.h>
#include <stdint.h>

using namespace nvcuda;

#define NB 2
#define CH 256
#define SV 32768L
#define NH 4
#define HD 64
#define SCALE_INV 0.0625f
#define EPS 1e-6f

__device__ __forceinline__ unsigned pack2(float a, float b) {
    __nv_bfloat162 t = __floats2bfloat162_rn(a, b);
    return *reinterpret_cast<unsigned*>(&t);
}

// ---------------- scratch ----------------
__device__ __align__(16) float g_attn   [NB * 256L * SV];
__device__ __align__(16) float g_praw   [NB * 256 * 512];
__device__ __align__(16) float g_pnorm  [NB * 256 * 512];
__device__ __align__(16) __nv_bfloat16 g_xB    [NB * 256L * SV];
__device__ __align__(16) __nv_bfloat16 g_qkvB  [NB * 768L * SV];
__device__ __align__(16) __nv_bfloat16 g_attnB [NB * 256L * SV];
__device__ __align__(16) __nv_bfloat16 g_ghi   [NB * 256L * SV];
__device__ __align__(16) __nv_bfloat16 g_glo   [NB * 256L * SV];
__device__ __align__(16) __nv_bfloat16 g_pooledB[NB * 256 * 512];
__device__ __align__(16) __nv_bfloat16 g_q2T   [NB * 4L * SV * 64];
__device__ __align__(16) __nv_bfloat16 g_kvT   [NB * 8L * 512 * 64];
__device__ __align__(16) __nv_bfloat16 g_Wqkv2B[NB * 768 * 256];
__device__ __align__(16) __nv_bfloat16 g_Wq2B  [NB * 256 * 256];
__device__ __align__(16) __nv_bfloat16 g_WkvB  [512 * 256];
__device__ __align__(16) __nv_bfloat16 g_WprojB[256 * 768];
__device__ float g_qkvb2[NB * 768];
__device__ float g_qb2  [NB * 256];
__device__ float g_part [NB * 2048 * 2];
__device__ float g_part2[NB * 64 * 2];
__device__ float g_aff  [6 * NB * 256];

// ---------------- cp.async ----------------
__device__ __forceinline__ void cp16(void* dst, const void* src) {
    unsigned d = (unsigned)__cvta_generic_to_shared(dst);
    asm volatile("cp.async.cg.shared.global [%0], [%1], 16;\n" :: "r"(d), "l"(src));
}
#define CP_COMMIT asm volatile("cp.async.commit_group;\n" ::: "memory")
#define CP_WAIT1  asm volatile("cp.async.wait_group 1;\n" ::: "memory")
#define CP_WAIT0  asm volatile("cp.async.wait_group 0;\n" ::: "memory")

// =========================================================================
// reductions / affine / conversions (per-batch via pointers)
// =========================================================================
__global__ void reduce1x_kernel(const float* __restrict__ buf, long per4,
                                float* __restrict__ part, __nv_bfloat16* __restrict__ outB) {
    const float4* p = reinterpret_cast<const float4*>(buf);
    uint2* ob = reinterpret_cast<uint2*>(outB);
    float s = 0.f, ss = 0.f;
    for (long i = (long)blockIdx.x * blockDim.x + threadIdx.x; i < per4;
         i += (long)gridDim.x * blockDim.x) {
        float4 v = p[i];
        s  += v.x + v.y + v.z + v.w;
        ss += v.x*v.x + v.y*v.y + v.z*v.z + v.w*v.w;
        uint2 r;
        r.x = pack2(v.x, v.y);
        r.y = pack2(v.z, v.w);
        ob[i] = r;
    }
    for (int o = 16; o; o >>= 1) {
        s  += __shfl_down_sync(0xffffffffu, s, o);
        ss += __shfl_down_sync(0xffffffffu, ss, o);
    }
    __shared__ float sh[64];
    int w = threadIdx.x >> 5;
    if ((threadIdx.x & 31) == 0) { sh[w] = s; sh[32 + w] = ss; }
    __syncthreads();
    if (threadIdx.x < 32) {
        int nw = blockDim.x >> 5;
        s  = (threadIdx.x < nw) ? sh[threadIdx.x]      : 0.f;
        ss = (threadIdx.x < nw) ? sh[32 + threadIdx.x] : 0.f;
        for (int o = 16; o; o >>= 1) {
            s  += __shfl_down_sync(0xffffffffu, s, o);
            ss += __shfl_down_sync(0xffffffffu, ss, o);
        }
        if (threadIdx.x == 0) {
            part[(size_t)blockIdx.x * 2 + 0] = s;
            part[(size_t)blockIdx.x * 2 + 1] = ss;
        }
    }
}

// fused pooled affine + stats partials (+ pnorm store)
__global__ void reduce1p_kernel(const float* __restrict__ praw,
                                const float* __restrict__ a, const float* __restrict__ d,
                                long per4, float* __restrict__ part, float* __restrict__ pnorm) {
    const float4* p = reinterpret_cast<const float4*>(praw);
    float4* ob = reinterpret_cast<float4*>(pnorm);
    float s = 0.f, ss = 0.f;
    for (long i = (long)blockIdx.x * blockDim.x + threadIdx.x; i < per4;
         i += (long)gridDim.x * blockDim.x) {
        int c = (int)(i >> 7);
        float aa = a[c], dd = d[c];
        float4 v = p[i];
        v.x = fmaf(aa, v.x, dd); v.y = fmaf(aa, v.y, dd);
        v.z = fmaf(aa, v.z, dd); v.w = fmaf(aa, v.w, dd);
        ob[i] = v;
        s  += v.x + v.y + v.z + v.w;
        ss += v.x*v.x + v.y*v.y + v.z*v.z + v.w*v.w;
    }
    for (int o = 16; o; o >>= 1) {
        s  += __shfl_down_sync(0xffffffffu, s, o);
        ss += __shfl_down_sync(0xffffffffu, ss, o);
    }
    __shared__ float sh[64];
    int w = threadIdx.x >> 5;
    if ((threadIdx.x & 31) == 0) { sh[w] = s; sh[32 + w] = ss; }
    __syncthreads();
    if (threadIdx.x < 32) {
        int nw = blockDim.x >> 5;
        s  = (threadIdx.x < nw) ? sh[threadIdx.x]      : 0.f;
        ss = (threadIdx.x < nw) ? sh[32 + threadIdx.x] : 0.f;
        for (int o = 16; o; o >>= 1) {
            s  += __shfl_down_sync(0xffffffffu, s, o);
            ss += __shfl_down_sync(0xffffffffu, ss, o);
        }
        if (threadIdx.x == 0) {
            part[(size_t)blockIdx.x * 2 + 0] = s;
            part[(size_t)blockIdx.x * 2 + 1] = ss;
        }
    }
}

__global__ void stats2affine_kernel(const float* __restrict__ part, int nb,
                                    const float* __restrict__ w, const float* __restrict__ b,
                                    float* __restrict__ a, float* __restrict__ d,
                                    float inv_cnt) {
    int tid = threadIdx.x;
    float s = 0.f, ss = 0.f;
    for (int i = tid; i < nb; i += 256) {
        s  += part[(size_t)i * 2 + 0];
        ss += part[(size_t)i * 2 + 1];
    }
    for (int o = 16; o; o >>= 1) {
        s  += __shfl_down_sync(0xffffffffu, s, o);
        ss += __shfl_down_sync(0xffffffffu, ss, o);
    }
    __shared__ float sh[16];
    __shared__ float sm_mean, sm_rstd;
    int wp = tid >> 5;
    if ((tid & 31) == 0) { sh[wp] = s; sh[8 + wp] = ss; }
    __syncthreads();
    if (tid < 32) {
        s  = (tid < 8) ? sh[tid]     : 0.f;
        ss = (tid < 8) ? sh[8 + tid] : 0.f;
        for (int o = 4; o; o >>= 1) {
            s  += __shfl_down_sync(0xffffffffu, s, o);
            ss += __shfl_down_sync(0xffffffffu, ss, o);
        }
        if (tid == 0) {
            float mean = s * inv_cnt;
            float var  = ss * inv_cnt - mean * mean;
            sm_mean = mean;
            sm_rstd = rsqrtf(var + EPS);
        }
    }
    __syncthreads();
    float mean = sm_mean, rstd = sm_rstd;
    a[tid] = w[tid] * rstd;
    d[tid] = b[tid] - mean * rstd * w[tid];
}

__global__ void convert_plain_kernel(const float* __restrict__ x, __nv_bfloat16* __restrict__ out) {
    size_t i8 = (size_t)blockIdx.x * blockDim.x + threadIdx.x;
    const float4* p = reinterpret_cast<const float4*>(x) + i8 * 2;
    float4 v0 = p[0], v1 = p[1];
    uint4 u;
    u.x = pack2(v0.x, v0.y);
    u.y = pack2(v0.z, v0.w);
    u.z = pack2(v1.x, v1.y);
    u.w = pack2(v1.z, v1.w);
    reinterpret_cast<uint4*>(out)[i8] = u;
}

__global__ void fold_kernel(const float* __restrict__ W, const float* __restrict__ bsrc,
                            const float* __restrict__ A, const float* __restrict__ D,
                            __nv_bfloat16* __restrict__ W2, float* __restrict__ b2) {
    int m = blockIdx.x, tid = threadIdx.x;
    float w = W[(size_t)m * 256 + tid];
    float aa = A[tid], dd = D[tid];
    W2[(size_t)m * 256 + tid] = __float2bfloat16(w * aa);
    float pr = w * dd;
    for (int o = 16; o; o >>= 1) pr += __shfl_down_sync(0xffffffffu, pr, o);
    __shared__ float sh[8];
    if ((tid & 31) == 0) sh[tid >> 5] = pr;
    __syncthreads();
    if (tid == 0) {
        float t = 0.f;
        #pragma unroll
        for (int i = 0; i < 8; i++) t += sh[i];
        b2[m] = bsrc[m] + t;
    }
}

__global__ void convert_pooled_kernel(const float* __restrict__ pooled,
                                      const float* __restrict__ a, const float* __restrict__ d,
                                      __nv_bfloat16* __restrict__ out) {
    size_t i4 = (size_t)blockIdx.x * blockDim.x + threadIdx.x;
    int c = (int)(i4 >> 7);
    float aa = a[c], dd = d[c];
    float4 v = reinterpret_cast<const float4*>(pooled)[i4];
    uint2 r;
    r.x = pack2(fmaf(aa, v.x, dd), fmaf(aa, v.y, dd));
    r.y = pack2(fmaf(aa, v.z, dd), fmaf(aa, v.w, dd));
    reinterpret_cast<uint2*>(out)[i4] = r;
}

__global__ void convert_weights_kernel(
    const float* __restrict__ kv_w, const float* __restrict__ proj_w,
    __nv_bfloat16* __restrict__ Wkv, __nv_bfloat16* __restrict__ Wproj) {
    int idx = blockIdx.x * blockDim.x + threadIdx.x;
    const int T1 = 512 * 256, T2 = T1 + 256 * 768;
    if (idx < T1) {
        Wkv[idx] = __float2bfloat16(kv_w[idx]);
    } else if (idx < T2) {
        int j = idx - T1;
        int m = j / 768, k = j % 768;
        float v = proj_w[m * 256 + (k & 255)];
        __nv_bfloat16 hi = __float2bfloat16(v);
        if (k >= 256 && k < 512) hi = __float2bfloat16(v - __bfloat162float(hi));
        Wproj[j] = hi;
    }
}

// =========================================================================
// wgemm3: BM=128, BN=128, BK=64, 3-stage cp.async, 256 threads, 2 blocks/SM.
// =========================================================================
#define WG_A_STG 9216
#define WG_B_STG 8704
#define WG_SMEM (3 * (WG_A_STG + WG_B_STG) * 2)

template<int MODE>
__global__ void __launch_bounds__(256, 2) wgemm3_kernel(
    const __nv_bfloat16* __restrict__ A,
    const __nv_bfloat16* __restrict__ B0, const __nv_bfloat16* __restrict__ B1,
    const float* __restrict__ bias,
    float* __restrict__ outF, __nv_bfloat16* __restrict__ outB,
    int M, int S, int KT, float qScale) {
    extern __shared__ __align__(16) char dsm[];
    __nv_bfloat16* As = (__nv_bfloat16*)dsm;
    __nv_bfloat16* Bs = (__nv_bfloat16*)(dsm + 3 * WG_A_STG * 2);
    float* Cs = (float*)dsm;

    int tid = threadIdx.x, warp = tid >> 5;
    int wm = warp >> 2, wn = warp & 3;
    int m0 = blockIdx.x * 128;
    int s0 = blockIdx.y * 128;

    wmma::fragment<wmma::accumulator, 16, 16, 16, float> acc[4][2];
    #pragma unroll
    for (int i = 0; i < 4; i++)
        #pragma unroll
        for (int j = 0; j < 2; j++) wmma::fill_fragment(acc[i][j], 0.f);

    const int NIT = KT >> 6;

    auto prefetch = [&](int it, int buf) {
        int ktL = it * 64;
        #pragma unroll
        for (int i = 0; i < 4; i++) {
            int c = tid + i * 256;
            int r = c >> 3, q = (c & 7) * 8;
            cp16(As + buf * WG_A_STG + r * 72 + q,
                 A + (size_t)(m0 + r) * KT + ktL + q);
        }
        const __nv_bfloat16* Bp = (ktL < 512) ? B0 : B1;
        int krow = ktL & 255;
        #pragma unroll
        for (int i = 0; i < 4; i++) {
            int c = tid + i * 256;
            int r = c >> 4, q = (c & 15) * 8;
            cp16(Bs + buf * WG_B_STG + r * 136 + q,
                 Bp + (size_t)(krow + r) * S + s0 + q);
        }
    };

    prefetch(0, 0); CP_COMMIT;
    if (NIT > 1) { prefetch(1, 1); CP_COMMIT; }

    int buf = 0;
    for (int it = 0; it < NIT; it++) {
        if (it + 1 < NIT) CP_WAIT1; else CP_WAIT0;
        __syncthreads();
        #pragma unroll
        for (int ks = 0; ks < 4; ks++) {
            wmma::fragment<wmma::matrix_a, 16, 16, 16, __nv_bfloat16, wmma::row_major> af[4];
            #pragma unroll
            for (int i = 0; i < 4; i++)
                wmma::load_matrix_sync(af[i], As + buf * WG_A_STG + (wm * 64 + i * 16) * 72 + ks * 16, 72);
            wmma::fragment<wmma::matrix_b, 16, 16, 16, __nv_bfloat16, wmma::row_major> bf[2];
            #pragma unroll
            for (int j = 0; j < 2; j++)
                wmma::load_matrix_sync(bf[j], Bs + buf * WG_B_STG + (ks * 16) * 136 + wn * 32 + j * 16, 136);
            #pragma unroll
            for (int i = 0; i < 4; i++)
                #pragma unroll
                for (int j = 0; j < 2; j++)
                    wmma::mma_sync(acc[i][j], af[i], bf[j], acc[i][j]);
        }
        if (it + 2 < NIT) {
            prefetch(it + 2, (buf + 2) % 3);
            CP_COMMIT;
        }
        buf = (buf + 1) % 3;
    }

    __syncthreads();

    if (MODE == 0) {
        #pragma unroll
        for (int i = 0; i < 4; i++)
            #pragma unroll
            for (int j = 0; j < 2; j++)
                wmma::store_matrix_sync(Cs + (wm * 64 + i * 16) * 132 + wn * 32 + j * 16,
                                        acc[i][j], 132, wmma::mem_row_major);
        __syncthreads();
        float* Ob = outF + (size_t)m0 * S;
        #pragma unroll
        for (int it = 0; it < 16; it++) {
            int idx = tid + it * 256;
            int r = idx >> 5, c4 = idx & 31;
            float bv = bias[m0 + r];
            float4 v = *reinterpret_cast<const float4*>(&Cs[r * 132 + c4 * 4]);
            v.x += bv; v.y += bv; v.z += bv; v.w += bv;
            *reinterpret_cast<float4*>(&Ob[(size_t)r * S + s0 + c4 * 4]) = v;
        }
    } else {
        #pragma unroll
        for (int i = 0; i < 4; i++)
            #pragma unroll
            for (int j = 0; j < 2; j++)
                wmma::store_matrix_sync(Cs + (wn * 32 + j * 16) * 136 + wm * 64 + i * 16,
                                        acc[i][j], 136, wmma::mem_col_major);
        __syncthreads();

        int dg = tid & 15;
        int gmb = m0 + dg * 8;
        float bias8[8];
        #pragma unroll
        for (int e = 0; e < 8; e++) bias8[e] = bias[gmb + e];

        float sc;
        int db = gmb & 63;
        __nv_bfloat16* hbase;
        if (MODE == 1) {
            int hb = gmb >> 6;
            sc = qScale;
            hbase = outB + ((size_t)hb * S + s0) * 64 + db;
        } else {
            int sel = gmb >> 8, head = (gmb >> 6) & 3;
            sc = (sel == 0) ? qScale : 1.f;
            hbase = outB + (((size_t)sel * 4 + head) * 512) * 4096 + db;
        }

        #pragma unroll
        for (int it = 0; it < 8; it++) {
            int sl = it * 16 + (tid >> 4);
            float4 lo = *reinterpret_cast<const float4*>(&Cs[sl * 136 + dg * 8]);
            float4 hi = *reinterpret_cast<const float4*>(&Cs[sl * 136 + dg * 8 + 4]);
            float f[8] = {lo.x, lo.y, lo.z, lo.w, hi.x, hi.y, hi.z, hi.w};
            #pragma unroll
            for (int e = 0; e < 8; e++) f[e] = (f[e] + bias8[e]) * sc;
            uint4 u;
            u.x = pack2(f[0], f[1]);
            u.y = pack2(f[2], f[3]);
            u.z = pack2(f[4], f[5]);
            u.w = pack2(f[6], f[7]);
            size_t off;
            if (MODE == 1) {
                off = (size_t)sl * 64;
            } else {
                int s = s0 + sl;
                int d5 = s & 31, w5 = (s >> 5) & 31, h5 = s >> 10;
                int window = ((h5 >> 2) * 8 + (w5 >> 2)) * 8 + (d5 >> 2);
                int token  = (((h5 & 3) * 4 + (w5 & 3)) * 4 + (d5 & 3));
                off = (size_t)window * 4096 + token * 64;
            }
            *reinterpret_cast<uint4*>(hbase + off) = u;
        }
    }
}

// =========================================================================
// Local windowed attention — per-batch pointers
// =========================================================================
__global__ void __launch_bounds__(128) local_attn_w_kernel(
    const __nv_bfloat16* __restrict__ qkvB, const float* __restrict__ x,
    float* __restrict__ attn, float* __restrict__ praw, float* __restrict__ part) {
    __shared__ __align__(16) __nv_bfloat16 QP[64 * 72];
    __shared__ __align__(16) __nv_bfloat16 Ks[64 * 72];
    __shared__ __align__(16) __nv_bfloat16 Vs[64 * 72];
    __shared__ __align__(16) float Sf[64 * 68];
    __shared__ float linv[64];
    __shared__ float rs[4], rss[4];

    int w = blockIdx.x, head = blockIdx.y;
    int tid = threadIdx.x, warp = tid >> 5;

    size_t base = ((size_t)head * 512 + w) * 4096;
    size_t step = (size_t)4 * 512 * 4096;
    const uint4* Qg = (const uint4*)(qkvB + base);
    const uint4* Kg = (const uint4*)(qkvB + base + step);
    const uint4* Vg = (const uint4*)(qkvB + base + 2 * step);

    #pragma unroll
    for (int i = 0; i < 4; i++) {
        int c = tid + i * 128;
        int r = c >> 3, q = c & 7;
        ((uint4*)(QP + r * 72))[q] = Qg[c];
        ((uint4*)(Ks + r * 72))[q] = Kg[c];
        ((uint4*)(Vs + r * 72))[q] = Vg[c];
    }
    __syncthreads();

    {
        int m = warp * 16;
        wmma::fragment<wmma::accumulator, 16, 16, 16, float> acc[4];
        #pragma unroll
        for (int j = 0; j < 4; j++) wmma::fill_fragment(acc[j], 0.f);
        #pragma unroll
        for (int kd = 0; kd < 4; kd++) {
            wmma::fragment<wmma::matrix_a, 16, 16, 16, __nv_bfloat16, wmma::row_major> af;
            wmma::load_matrix_sync(af, QP + m * 72 + kd * 16, 72);
            #pragma unroll
            for (int j = 0; j < 4; j++) {
                wmma::fragment<wmma::matrix_b, 16, 16, 16, __nv_bfloat16, wmma::col_major> bf;
                wmma::load_matrix_sync(bf, Ks + (j * 16) * 72 + kd * 16, 72);
                wmma::mma_sync(acc[j], af, bf, acc[j]);
            }
        }
        #pragma unroll
        for (int j = 0; j < 4; j++)
            wmma::store_matrix_sync(Sf + m * 68 + j * 16, acc[j], 68, wmma::mem_row_major);
    }
    __syncthreads();

    {
        int r = tid >> 1, hf = tid & 1;
        const float* srow = Sf + r * 68 + hf * 32;
        float ls = 0.f;
        __nv_bfloat16* prow = QP + r * 72 + hf * 32;
        #pragma unroll
        for (int j = 0; j < 32; j++) {
            float p = __expf(srow[j]);
            ls += p;
            prow[j] = __float2bfloat16(p);
        }
        ls += __shfl_xor_sync(0xffffffffu, ls, 1);
        if (hf == 0) linv[r] = 1.f / ls;
    }
    __syncthreads();

    {
        int m = warp * 16;
        wmma::fragment<wmma::accumulator, 16, 16, 16, float> acc[4];
        #pragma unroll
        for (int j = 0; j < 4; j++) wmma::fill_fragment(acc[j], 0.f);
        #pragma unroll
        for (int kk = 0; kk < 4; kk++) {
            wmma::fragment<wmma::matrix_a, 16, 16, 16, __nv_bfloat16, wmma::row_major> af;
            wmma::load_matrix_sync(af, QP + m * 72 + kk * 16, 72);
            #pragma unroll
            for (int j = 0; j < 4; j++) {
                wmma::fragment<wmma::matrix_b, 16, 16, 16, __nv_bfloat16, wmma::row_major> bf;
                wmma::load_matrix_sync(bf, Vs + (kk * 16) * 72 + j * 16, 72);
                wmma::mma_sync(acc[j], af, bf, acc[j]);
            }
        }
        #pragma unroll
        for (int j = 0; j < 4; j++)
            wmma::store_matrix_sync(Sf + m * 68 + j * 16, acc[j], 68, wmma::mem_row_major);
    }
    __syncthreads();

    int wh = w >> 6, ww = (w >> 3) & 7, wd = w & 7;
    int base_s = wh * 4096 + ww * 128 + wd * 4;
    int chb = head * 64;
    float s_acc = 0.f, ss_acc = 0.f;
    #pragma unroll
    for (int it = 0; it < 8; it++) {
        int idx = tid + it * 128;
        int d = idx >> 4, tg = idx & 15;
        int i_ = tg >> 2, j_ = tg & 3;
        int s = base_s + i_ * 1024 + j_ * 32;
        int t0 = tg * 4;
        size_t g = ((size_t)(chb + d)) * SV + s;
        float4 xv = *reinterpret_cast<const float4*>(x + g);
        float4 ov;
        ov.x = fmaf(Sf[(t0 + 0) * 68 + d], linv[t0 + 0], xv.x);
        ov.y = fmaf(Sf[(t0 + 1) * 68 + d], linv[t0 + 1], xv.y);
        ov.z = fmaf(Sf[(t0 + 2) * 68 + d], linv[t0 + 2], xv.z);
        ov.w = fmaf(Sf[(t0 + 3) * 68 + d], linv[t0 + 3], xv.w);
        *reinterpret_cast<float4*>(attn + g) = ov;
        float ps = ov.x + ov.y + ov.z + ov.w;
        s_acc  += ps;
        ss_acc += ov.x*ov.x + ov.y*ov.y + ov.z*ov.z + ov.w*ov.w;
        #pragma unroll
        for (int o = 8; o; o >>= 1) ps += __shfl_down_sync(0xffffffffu, ps, o);
        if ((tid & 15) == 0)
            praw[((size_t)(chb + d)) * 512 + w] = ps * (1.f / 64.f);
    }
    #pragma unroll
    for (int o = 16; o; o >>= 1) {
        s_acc  += __shfl_down_sync(0xffffffffu, s_acc, o);
        ss_acc += __shfl_down_sync(0xffffffffu, ss_acc, o);
    }
    if ((tid & 31) == 0) { rs[warp] = s_acc; rss[warp] = ss_acc; }
    __syncthreads();
    if (tid == 0) {
        size_t pi = (size_t)head * 512 + w;
        part[pi * 2 + 0] = rs[0] + rs[1] + rs[2] + rs[3];
        part[pi * 2 + 1] = rss[0] + rss[1] + rss[2] + rss[3];
    }
}

// =========================================================================
// Global attention — per-batch pointers
// =========================================================================
#define GA_SMEM 109056

__global__ void __launch_bounds__(256, 2) gattn_kernel(
    const __nv_bfloat16* __restrict__ q2T, const __nv_bfloat16* __restrict__ kvT,
    const float* __restrict__ attn,
    const float* __restrict__ A1, const float* __restrict__ D1,
    __nv_bfloat16* __restrict__ ghi, __nv_bfloat16* __restrict__ glo) {
    extern __shared__ __align__(16) char sm[];
    __nv_bfloat16* Qs = (__nv_bfloat16*)sm;
    __nv_bfloat16* Ks = Qs + 128 * 72;
    __nv_bfloat16* Vs = Ks + 2 * 64 * 72;
    __nv_bfloat16* Ps = Vs + 2 * 64 * 72;
    float* Sf   = (float*)(Ps + 128 * 72);
    float* lrow = Sf + 128 * 68;

    int tid = threadIdx.x, warp = tid >> 5;
    int h = blockIdx.y;
    int s0 = blockIdx.x * 128;

    const uint4* Qg = (const uint4*)(q2T + ((size_t)h * SV + s0) * 64);
    const __nv_bfloat16* Kg = kvT + ((size_t)h * 512) * 64;
    const __nv_bfloat16* Vg = kvT + ((size_t)(4 + h) * 512) * 64;

    auto prefetchKV = [&](int ch, int b) {
        #pragma unroll
        for (int i = 0; i < 2; i++) {
            int idx = tid + i * 256;
            int r = idx >> 3, c = (idx & 7) * 8;
            cp16(Ks + b * 4608 + r * 72 + c, Kg + (size_t)(ch * 64 + r) * 64 + c);
            cp16(Vs + b * 4608 + r * 72 + c, Vg + (size_t)(ch * 64 + r) * 64 + c);
        }
    };

    prefetchKV(0, 0); CP_COMMIT;

    #pragma unroll
    for (int i = 0; i < 4; i++) {
        int idx = tid + i * 256;
        int r = idx >> 3, c = idx & 7;
        ((uint4*)(Qs + r * 72))[c] = Qg[r * 8 + c];
    }
    if (tid < 128) lrow[tid] = 0.f;

    int pm = warp >> 1, pn = warp & 1;
    wmma::fragment<wmma::accumulator, 16, 16, 16, float> acc_o[2][2];
    #pragma unroll
    for (int i = 0; i < 2; i++)
        #pragma unroll
        for (int j = 0; j < 2; j++) wmma::fill_fragment(acc_o[i][j], 0.f);

    for (int ch = 0; ch < 8; ch++) {
        int b = ch & 1;
        CP_WAIT0;
        __syncthreads();

        {
            int m = warp * 16;
            wmma::fragment<wmma::accumulator, 16, 16, 16, float> acc[4];
            #pragma unroll
            for (int j = 0; j < 4; j++) wmma::fill_fragment(acc[j], 0.f);
            #pragma unroll
            for (int kd = 0; kd < 4; kd++) {
                wmma::fragment<wmma::matrix_a, 16, 16, 16, __nv_bfloat16, wmma::row_major> af;
                wmma::load_matrix_sync(af, Qs + m * 72 + kd * 16, 72);
                #pragma unroll
                for (int j = 0; j < 4; j++) {
                    wmma::fragment<wmma::matrix_b, 16, 16, 16, __nv_bfloat16, wmma::col_major> bf;
                    wmma::load_matrix_sync(bf, Ks + b * 4608 + (j * 16) * 72 + kd * 16, 72);
                    wmma::mma_sync(acc[j], af, bf, acc[j]);
                }
            }
            #pragma unroll
            for (int j = 0; j < 4; j++)
                wmma::store_matrix_sync(Sf + m * 68 + j * 16, acc[j], 68, wmma::mem_row_major);
        }
        __syncthreads();

        {
            int r = tid >> 1, hf = tid & 1;
            const float* srow = Sf + r * 68 + hf * 32;
            float ls = 0.f;
            __nv_bfloat16* prow = Ps + r * 72 + hf * 32;
            #pragma unroll
            for (int j = 0; j < 32; j++) {
                float p = __expf(srow[j]);
                ls += p;
                prow[j] = __float2bfloat16(p);
            }
            ls += __shfl_xor_sync(0xffffffffu, ls, 1);
            if (hf == 0) lrow[r] += ls;
        }
        __syncthreads();

        if (ch + 1 < 8) {
            prefetchKV(ch + 1, b ^ 1);
            CP_COMMIT;
        }

        {
            #pragma unroll
            for (int kk = 0; kk < 4; kk++) {
                wmma::fragment<wmma::matrix_a, 16, 16, 16, __nv_bfloat16, wmma::row_major> af[2];
                #pragma unroll
                for (int i = 0; i < 2; i++)
                    wmma::load_matrix_sync(af[i], Ps + (pm * 32 + i * 16) * 72 + kk * 16, 72);
                wmma::fragment<wmma::matrix_b, 16, 16, 16, __nv_bfloat16, wmma::row_major> bf[2];
                #pragma unroll
                for (int j = 0; j < 2; j++)
                    wmma::load_matrix_sync(bf[j], Vs + b * 4608 + (kk * 16) * 72 + pn * 32 + j * 16, 72);
                #pragma unroll
                for (int i = 0; i < 2; i++)
                    #pragma unroll
                    for (int j = 0; j < 2; j++)
                        wmma::mma_sync(acc_o[i][j], af[i], bf[j], acc_o[i][j]);
            }
        }
    }

    __syncthreads();
    #pragma unroll
    for (int i = 0; i < 2; i++)
        #pragma unroll
        for (int j = 0; j < 2; j++)
            wmma::store_matrix_sync(Sf + (pm * 32 + i * 16) * 68 + pn * 32 + j * 16,
                                    acc_o[i][j], 68, wmma::mem_row_major);
    __syncthreads();

    #pragma unroll
    for (int i = 0; i < 32; i++) {
        int idx = tid + i * 256;
        int r = idx & 127, d = idx >> 7;
        int cch = h * 64 + d;
        float v = Sf[r * 68 + d] / lrow[r];
        size_t gi = ((size_t)cch) * SV + s0 + r;
        float t = v + fmaf(A1[cch], attn[gi], D1[cch]);
        __nv_bfloat16 hi = __float2bfloat16(t);
        ghi[gi] = hi;
        glo[gi] = __float2bfloat16(t - __bfloat162float(hi));
    }
}

// =========================================================================
// host launch — 2 batch streams + 2 side streams, intra-batch forking
// =========================================================================
extern "C" void kernel_launch(void* const* d_in, const int* in_sizes, int n_in,
                              void* d_out, int out_size) {
    const float* x      = (const float*)d_in[0];
    const float* qkv_w  = (const float*)d_in[1];
    const float* qkv_b  = (const float*)d_in[2];
    const float* norm_w = (const float*)d_in[3];
    const float* norm_b = (const float*)d_in[4];
    const float* anorm_w= (const float*)d_in[5];
    const float* anorm_b= (const float*)d_in[6];
    const float* dnorm_w= (const float*)d_in[7];
    const float* dnorm_b= (const float*)d_in[8];
    const float* q_w    = (const float*)d_in[9];
    const float* q_b    = (const float*)d_in[10];
    const float* kv_w   = (const float*)d_in[11];
    const float* kv_b   = (const float*)d_in[12];
    const float* proj_w = (const float*)d_in[13];
    const float* proj_b = (const float*)d_in[14];
    float* out = (float*)d_out;

    float *attn, *praw, *pnorm, *part, *part2, *aff, *qkvb2, *qb2;
    __nv_bfloat16 *xB, *qkvB, *attnB, *ghi, *glo, *pooledB, *q2T, *kvT;
    __nv_bfloat16 *Wqkv2B, *Wq2B, *WkvB, *WprojB;
    cudaGetSymbolAddress((void**)&attn,    g_attn);
    cudaGetSymbolAddress((void**)&praw,    g_praw);
    cudaGetSymbolAddress((void**)&pnorm,   g_pnorm);
    cudaGetSymbolAddress((void**)&xB,      g_xB);
    cudaGetSymbolAddress((void**)&qkvB,    g_qkvB);
    cudaGetSymbolAddress((void**)&attnB,   g_attnB);
    cudaGetSymbolAddress((void**)&ghi,     g_ghi);
    cudaGetSymbolAddress((void**)&glo,     g_glo);
    cudaGetSymbolAddress((void**)&pooledB, g_pooledB);
    cudaGetSymbolAddress((void**)&q2T,     g_q2T);
    cudaGetSymbolAddress((void**)&kvT,     g_kvT);
    cudaGetSymbolAddress((void**)&Wqkv2B,  g_Wqkv2B);
    cudaGetSymbolAddress((void**)&Wq2B,    g_Wq2B);
    cudaGetSymbolAddress((void**)&WkvB,    g_WkvB);
    cudaGetSymbolAddress((void**)&WprojB,  g_WprojB);
    cudaGetSymbolAddress((void**)&qkvb2,   g_qkvb2);
    cudaGetSymbolAddress((void**)&qb2,     g_qb2);
    cudaGetSymbolAddress((void**)&part,    g_part);
    cudaGetSymbolAddress((void**)&part2,   g_part2);
    cudaGetSymbolAddress((void**)&aff,     g_aff);

    static cudaStream_t s1 = nullptr, s2 = nullptr, s3 = nullptr;
    static cudaEvent_t ev0, evW, evDone;
    static cudaEvent_t evLA[2], evCvt[2], evA1[2], evKV[2];
    static bool init_done = false;
    if (!init_done) {
        cudaFuncSetAttribute(gattn_kernel, cudaFuncAttributeMaxDynamicSharedMemorySize, GA_SMEM);
        cudaFuncSetAttribute(wgemm3_kernel<0>, cudaFuncAttributeMaxDynamicSharedMemorySize, WG_SMEM);
        cudaFuncSetAttribute(wgemm3_kernel<1>, cudaFuncAttributeMaxDynamicSharedMemorySize, WG_SMEM);
        cudaFuncSetAttribute(wgemm3_kernel<2>, cudaFuncAttributeMaxDynamicSharedMemorySize, WG_SMEM);
        cudaStreamCreateWithFlags(&s1, cudaStreamNonBlocking);
        cudaStreamCreateWithFlags(&s2, cudaStreamNonBlocking);
        cudaStreamCreateWithFlags(&s3, cudaStreamNonBlocking);
        cudaEventCreateWithFlags(&ev0,    cudaEventDisableTiming);
        cudaEventCreateWithFlags(&evW,    cudaEventDisableTiming);
        cudaEventCreateWithFlags(&evDone, cudaEventDisableTiming);
        for (int i = 0; i < 2; i++) {
            cudaEventCreateWithFlags(&evLA[i],  cudaEventDisableTiming);
            cudaEventCreateWithFlags(&evCvt[i], cudaEventDisableTiming);
            cudaEventCreateWithFlags(&evA1[i],  cudaEventDisableTiming);
            cudaEventCreateWithFlags(&evKV[i],  cudaEventDisableTiming);
        }
        init_done = true;
    }

    // fork all side streams from capture origin
    cudaEventRecord(ev0, 0);
    cudaStreamWaitEvent(s1, ev0, 0);
    cudaStreamWaitEvent(s2, ev0, 0);
    cudaStreamWaitEvent(s3, ev0, 0);

    // weights convert once on s2 (batch0's side stream)
    convert_weights_kernel<<<1280, 256, 0, s2>>>(kv_w, proj_w, WkvB, WprojB);
    cudaEventRecord(evW, s2);

    for (int n = 0; n < NB; n++) {
        cudaStream_t mSt = (n == 0) ? (cudaStream_t)0 : s1;
        cudaStream_t sSt = (n == 0) ? s2 : s3;
        const float* x_n       = x      + (size_t)n * 256 * SV;
        float* attn_n          = attn   + (size_t)n * 256 * SV;
        float* praw_n          = praw   + (size_t)n * 256 * 512;
        float* pnorm_n         = pnorm  + (size_t)n * 256 * 512;
        __nv_bfloat16* xB_n    = xB     + (size_t)n * 256 * SV;
        __nv_bfloat16* qkvB_n  = qkvB   + (size_t)n * 768 * SV;
        __nv_bfloat16* attnB_n = attnB  + (size_t)n * 256 * SV;
        __nv_bfloat16* ghi_n   = ghi    + (size_t)n * 256 * SV;
        __nv_bfloat16* glo_n   = glo    + (size_t)n * 256 * SV;
        __nv_bfloat16* pooledB_n = pooledB + (size_t)n * 256 * 512;
        __nv_bfloat16* q2T_n   = q2T    + (size_t)n * 4 * SV * 64;
        __nv_bfloat16* kvT_n   = kvT    + (size_t)n * 8 * 512 * 64;
        __nv_bfloat16* Wqkv2_n = Wqkv2B + (size_t)n * 768 * 256;
        __nv_bfloat16* Wq2_n   = Wq2B   + (size_t)n * 256 * 256;
        float* qkvb2_n = qkvb2 + n * 768;
        float* qb2_n   = qb2   + n * 256;
        float* part_n  = part  + (size_t)n * 2048 * 2;
        float* part2_n = part2 + (size_t)n * 64 * 2;
        float* A0n = aff + n * 256;          float* D0n = aff + 512 + n * 256;
        float* A1n = aff + 1024 + n * 256;   float* D1n = aff + 1536 + n * 256;
        float* A2n = aff + 2048 + n * 256;   float* D2n = aff + 2560 + n * 256;
        float* out_n = out + (size_t)n * 256 * SV;

        // main: x stats + fold + qkv GEMM + local attention
        reduce1x_kernel<<<512, 256, 0, mSt>>>(x_n, 256L * SV / 4, part_n, xB_n);
        stats2affine_kernel<<<1, 256, 0, mSt>>>(part_n, 512, norm_w, norm_b, A0n, D0n,
                                                1.f / (256.f * 32768.f));
        fold_kernel<<<768, 256, 0, mSt>>>(qkv_w, qkv_b, A0n, D0n, Wqkv2_n, qkvb2_n);
        wgemm3_kernel<2><<<dim3(6, 256), 256, WG_SMEM, mSt>>>(
            Wqkv2_n, xB_n, xB_n, qkvb2_n, nullptr, qkvB_n, 768, (int)SV, 256, SCALE_INV);
        local_attn_w_kernel<<<dim3(512, NH), 128, 0, mSt>>>(qkvB_n, x_n, attn_n, praw_n, part_n);
        cudaEventRecord(evLA[n], mSt);

        // side: attnB conversion (stats-independent)
        cudaStreamWaitEvent(sSt, evLA[n], 0);
        convert_plain_kernel<<<4096, 256, 0, sSt>>>(attn_n, attnB_n);
        cudaEventRecord(evCvt[n], sSt);

        // main: anorm affine + q fold
        stats2affine_kernel<<<1, 256, 0, mSt>>>(part_n, 2048, anorm_w, anorm_b, A1n, D1n,
                                                1.f / (256.f * 32768.f));
        cudaEventRecord(evA1[n], mSt);
        fold_kernel<<<256, 256, 0, mSt>>>(q_w, q_b, A1n, D1n, Wq2_n, qb2_n);

        // side: pooled chain (needs A1) + kv GEMM
        cudaStreamWaitEvent(sSt, evA1[n], 0);
        reduce1p_kernel<<<32, 256, 0, sSt>>>(praw_n, A1n, D1n, 256L * 512 / 4, part2_n, pnorm_n);
        stats2affine_kernel<<<1, 256, 0, sSt>>>(part2_n, 32, dnorm_w, dnorm_b, A2n, D2n,
                                                1.f / (256.f * 512.f));
        convert_pooled_kernel<<<128, 256, 0, sSt>>>(pnorm_n, A2n, D2n, pooledB_n);
        if (n == 1) cudaStreamWaitEvent(sSt, evW, 0);   // s3 needs WkvB; s2 has it in-order
        wgemm3_kernel<1><<<dim3(4, 4), 256, WG_SMEM, sSt>>>(
            WkvB, pooledB_n, pooledB_n, kv_b, nullptr, kvT_n, 512, 512, 256, 1.f);
        cudaEventRecord(evKV[n], sSt);

        // main: q GEMM -> gattn -> proj
        cudaStreamWaitEvent(mSt, evCvt[n], 0);
        wgemm3_kernel<1><<<dim3(2, 256), 256, WG_SMEM, mSt>>>(
            Wq2_n, attnB_n, attnB_n, qb2_n, nullptr, q2T_n, 256, (int)SV, 256, SCALE_INV);
        cudaStreamWaitEvent(mSt, evKV[n], 0);
        gattn_kernel<<<dim3(256, NH), 256, GA_SMEM, mSt>>>(
            q2T_n, kvT_n, attn_n, A1n, D1n, ghi_n, glo_n);
        cudaStreamWaitEvent(mSt, evW, 0);               // proj needs WprojB
        wgemm3_kernel<0><<<dim3(2, 256), 256, WG_SMEM, mSt>>>(
            WprojB, ghi_n, glo_n, proj_b, out_n, nullptr, 256, (int)SV, 768, 1.f);
    }

    // join batch1 main stream into default
    cudaEventRecord(evDone, s1);
    cudaStreamWaitEvent(0, evDone, 0);
}

// round 17
// speedup vs baseline: 1.0651x; 1.0051x over previous
#include <cuda_runtime.h>
#include <cuda_bf16.h>
#include <mma.h>
#include <math.h>
#include <stdint.h>

using namespace nvcuda;

#define NB 2
#define CH 256
#define SV 32768L
#define NH 4
#define HD 64
#define SCALE_INV 0.0625f
#define EPS 1e-6f

__device__ __forceinline__ unsigned pack2(float a, float b) {
    __nv_bfloat162 t = __floats2bfloat162_rn(a, b);
    return *reinterpret_cast<unsigned*>(&t);
}

// ---------------- scratch ----------------
__device__ __align__(16) float g_attn   [NB * 256L * SV];
__device__ __align__(16) float g_praw   [NB * 256 * 512];
__device__ __align__(16) float g_pnorm  [NB * 256 * 512];
__device__ __align__(16) __nv_bfloat16 g_xB    [NB * 256L * SV];
__device__ __align__(16) __nv_bfloat16 g_qkvB  [NB * 768L * SV];
__device__ __align__(16) __nv_bfloat16 g_attnB [NB * 256L * SV];
__device__ __align__(16) __nv_bfloat16 g_ghi   [NB * 256L * SV];
__device__ __align__(16) __nv_bfloat16 g_glo   [NB * 256L * SV];
__device__ __align__(16) __nv_bfloat16 g_pooledB[NB * 256 * 512];
__device__ __align__(16) __nv_bfloat16 g_q2T   [NB * 4L * SV * 64];
__device__ __align__(16) __nv_bfloat16 g_kvT   [NB * 8L * 512 * 64];
__device__ __align__(16) __nv_bfloat16 g_Wqkv2B[NB * 768 * 256];
__device__ __align__(16) __nv_bfloat16 g_Wq2B  [NB * 256 * 256];
__device__ __align__(16) __nv_bfloat16 g_WkvB  [512 * 256];
__device__ __align__(16) __nv_bfloat16 g_WprojB[256 * 768];
__device__ float g_qkvb2[NB * 768];
__device__ float g_qb2  [NB * 256];
__device__ float g_part [NB * 2048 * 2];
__device__ float g_part2[NB * 64 * 2];
__device__ float g_aff  [6 * NB * 256];

// ---------------- cp.async ----------------
__device__ __forceinline__ void cp16(void* dst, const void* src) {
    unsigned d = (unsigned)__cvta_generic_to_shared(dst);
    asm volatile("cp.async.cg.shared.global [%0], [%1], 16;\n" :: "r"(d), "l"(src));
}
#define CP_COMMIT asm volatile("cp.async.commit_group;\n" ::: "memory")
#define CP_WAIT1  asm volatile("cp.async.wait_group 1;\n" ::: "memory")
#define CP_WAIT0  asm volatile("cp.async.wait_group 0;\n" ::: "memory")

// =========================================================================
// reductions / affine / conversions (per-batch via pointers)
// =========================================================================
__global__ void reduce1x_kernel(const float* __restrict__ buf, long per4,
                                float* __restrict__ part, __nv_bfloat16* __restrict__ outB) {
    const float4* p = reinterpret_cast<const float4*>(buf);
    uint2* ob = reinterpret_cast<uint2*>(outB);
    float s = 0.f, ss = 0.f;
    for (long i = (long)blockIdx.x * blockDim.x + threadIdx.x; i < per4;
         i += (long)gridDim.x * blockDim.x) {
        float4 v = p[i];
        s  += v.x + v.y + v.z + v.w;
        ss += v.x*v.x + v.y*v.y + v.z*v.z + v.w*v.w;
        uint2 r;
        r.x = pack2(v.x, v.y);
        r.y = pack2(v.z, v.w);
        ob[i] = r;
    }
    for (int o = 16; o; o >>= 1) {
        s  += __shfl_down_sync(0xffffffffu, s, o);
        ss += __shfl_down_sync(0xffffffffu, ss, o);
    }
    __shared__ float sh[64];
    int w = threadIdx.x >> 5;
    if ((threadIdx.x & 31) == 0) { sh[w] = s; sh[32 + w] = ss; }
    __syncthreads();
    if (threadIdx.x < 32) {
        int nw = blockDim.x >> 5;
        s  = (threadIdx.x < nw) ? sh[threadIdx.x]      : 0.f;
        ss = (threadIdx.x < nw) ? sh[32 + threadIdx.x] : 0.f;
        for (int o = 16; o; o >>= 1) {
            s  += __shfl_down_sync(0xffffffffu, s, o);
            ss += __shfl_down_sync(0xffffffffu, ss, o);
        }
        if (threadIdx.x == 0) {
            part[(size_t)blockIdx.x * 2 + 0] = s;
            part[(size_t)blockIdx.x * 2 + 1] = ss;
        }
    }
}

// fused pooled affine + stats partials (+ pnorm store)
__global__ void reduce1p_kernel(const float* __restrict__ praw,
                                const float* __restrict__ a, const float* __restrict__ d,
                                long per4, float* __restrict__ part, float* __restrict__ pnorm) {
    const float4* p = reinterpret_cast<const float4*>(praw);
    float4* ob = reinterpret_cast<float4*>(pnorm);
    float s = 0.f, ss = 0.f;
    for (long i = (long)blockIdx.x * blockDim.x + threadIdx.x; i < per4;
         i += (long)gridDim.x * blockDim.x) {
        int c = (int)(i >> 7);
        float aa = a[c], dd = d[c];
        float4 v = p[i];
        v.x = fmaf(aa, v.x, dd); v.y = fmaf(aa, v.y, dd);
        v.z = fmaf(aa, v.z, dd); v.w = fmaf(aa, v.w, dd);
        ob[i] = v;
        s  += v.x + v.y + v.z + v.w;
        ss += v.x*v.x + v.y*v.y + v.z*v.z + v.w*v.w;
    }
    for (int o = 16; o; o >>= 1) {
        s  += __shfl_down_sync(0xffffffffu, s, o);
        ss += __shfl_down_sync(0xffffffffu, ss, o);
    }
    __shared__ float sh[64];
    int w = threadIdx.x >> 5;
    if ((threadIdx.x & 31) == 0) { sh[w] = s; sh[32 + w] = ss; }
    __syncthreads();
    if (threadIdx.x < 32) {
        int nw = blockDim.x >> 5;
        s  = (threadIdx.x < nw) ? sh[threadIdx.x]      : 0.f;
        ss = (threadIdx.x < nw) ? sh[32 + threadIdx.x] : 0.f;
        for (int o = 16; o; o >>= 1) {
            s  += __shfl_down_sync(0xffffffffu, s, o);
            ss += __shfl_down_sync(0xffffffffu, ss, o);
        }
        if (threadIdx.x == 0) {
            part[(size_t)blockIdx.x * 2 + 0] = s;
            part[(size_t)blockIdx.x * 2 + 1] = ss;
        }
    }
}

__global__ void stats2affine_kernel(const float* __restrict__ part, int nb,
                                    const float* __restrict__ w, const float* __restrict__ b,
                                    float* __restrict__ a, float* __restrict__ d,
                                    float inv_cnt) {
    int tid = threadIdx.x;
    float s = 0.f, ss = 0.f;
    for (int i = tid; i < nb; i += 256) {
        s  += part[(size_t)i * 2 + 0];
        ss += part[(size_t)i * 2 + 1];
    }
    for (int o = 16; o; o >>= 1) {
        s  += __shfl_down_sync(0xffffffffu, s, o);
        ss += __shfl_down_sync(0xffffffffu, ss, o);
    }
    __shared__ float sh[16];
    __shared__ float sm_mean, sm_rstd;
    int wp = tid >> 5;
    if ((tid & 31) == 0) { sh[wp] = s; sh[8 + wp] = ss; }
    __syncthreads();
    if (tid < 32) {
        s  = (tid < 8) ? sh[tid]     : 0.f;
        ss = (tid < 8) ? sh[8 + tid] : 0.f;
        for (int o = 4; o; o >>= 1) {
            s  += __shfl_down_sync(0xffffffffu, s, o);
            ss += __shfl_down_sync(0xffffffffu, ss, o);
        }
        if (tid == 0) {
            float mean = s * inv_cnt;
            float var  = ss * inv_cnt - mean * mean;
            sm_mean = mean;
            sm_rstd = rsqrtf(var + EPS);
        }
    }
    __syncthreads();
    float mean = sm_mean, rstd = sm_rstd;
    a[tid] = w[tid] * rstd;
    d[tid] = b[tid] - mean * rstd * w[tid];
}

__global__ void fold_kernel(const float* __restrict__ W, const float* __restrict__ bsrc,
                            const float* __restrict__ A, const float* __restrict__ D,
                            __nv_bfloat16* __restrict__ W2, float* __restrict__ b2) {
    int m = blockIdx.x, tid = threadIdx.x;
    float w = W[(size_t)m * 256 + tid];
    float aa = A[tid], dd = D[tid];
    W2[(size_t)m * 256 + tid] = __float2bfloat16(w * aa);
    float pr = w * dd;
    for (int o = 16; o; o >>= 1) pr += __shfl_down_sync(0xffffffffu, pr, o);
    __shared__ float sh[8];
    if ((tid & 31) == 0) sh[tid >> 5] = pr;
    __syncthreads();
    if (tid == 0) {
        float t = 0.f;
        #pragma unroll
        for (int i = 0; i < 8; i++) t += sh[i];
        b2[m] = bsrc[m] + t;
    }
}

__global__ void convert_pooled_kernel(const float* __restrict__ pooled,
                                      const float* __restrict__ a, const float* __restrict__ d,
                                      __nv_bfloat16* __restrict__ out) {
    size_t i4 = (size_t)blockIdx.x * blockDim.x + threadIdx.x;
    int c = (int)(i4 >> 7);
    float aa = a[c], dd = d[c];
    float4 v = reinterpret_cast<const float4*>(pooled)[i4];
    uint2 r;
    r.x = pack2(fmaf(aa, v.x, dd), fmaf(aa, v.y, dd));
    r.y = pack2(fmaf(aa, v.z, dd), fmaf(aa, v.w, dd));
    reinterpret_cast<uint2*>(out)[i4] = r;
}

__global__ void convert_weights_kernel(
    const float* __restrict__ kv_w, const float* __restrict__ proj_w,
    __nv_bfloat16* __restrict__ Wkv, __nv_bfloat16* __restrict__ Wproj) {
    int idx = blockIdx.x * blockDim.x + threadIdx.x;
    const int T1 = 512 * 256, T2 = T1 + 256 * 768;
    if (idx < T1) {
        Wkv[idx] = __float2bfloat16(kv_w[idx]);
    } else if (idx < T2) {
        int j = idx - T1;
        int m = j / 768, k = j % 768;
        float v = proj_w[m * 256 + (k & 255)];
        __nv_bfloat16 hi = __float2bfloat16(v);
        if (k >= 256 && k < 512) hi = __float2bfloat16(v - __bfloat162float(hi));
        Wproj[j] = hi;
    }
}

// =========================================================================
// wgemm3: BM=128, BN=128, BK=64, 3-stage cp.async, 256 threads, 2 blocks/SM.
// =========================================================================
#define WG_A_STG 9216
#define WG_B_STG 8704
#define WG_SMEM (3 * (WG_A_STG + WG_B_STG) * 2)

template<int MODE>
__global__ void __launch_bounds__(256, 2) wgemm3_kernel(
    const __nv_bfloat16* __restrict__ A,
    const __nv_bfloat16* __restrict__ B0, const __nv_bfloat16* __restrict__ B1,
    const float* __restrict__ bias,
    float* __restrict__ outF, __nv_bfloat16* __restrict__ outB,
    int M, int S, int KT, float qScale) {
    extern __shared__ __align__(16) char dsm[];
    __nv_bfloat16* As = (__nv_bfloat16*)dsm;
    __nv_bfloat16* Bs = (__nv_bfloat16*)(dsm + 3 * WG_A_STG * 2);
    float* Cs = (float*)dsm;

    int tid = threadIdx.x, warp = tid >> 5;
    int wm = warp >> 2, wn = warp & 3;
    int m0 = blockIdx.x * 128;
    int s0 = blockIdx.y * 128;

    wmma::fragment<wmma::accumulator, 16, 16, 16, float> acc[4][2];
    #pragma unroll
    for (int i = 0; i < 4; i++)
        #pragma unroll
        for (int j = 0; j < 2; j++) wmma::fill_fragment(acc[i][j], 0.f);

    const int NIT = KT >> 6;

    auto prefetch = [&](int it, int buf) {
        int ktL = it * 64;
        #pragma unroll
        for (int i = 0; i < 4; i++) {
            int c = tid + i * 256;
            int r = c >> 3, q = (c & 7) * 8;
            cp16(As + buf * WG_A_STG + r * 72 + q,
                 A + (size_t)(m0 + r) * KT + ktL + q);
        }
        const __nv_bfloat16* Bp = (ktL < 512) ? B0 : B1;
        int krow = ktL & 255;
        #pragma unroll
        for (int i = 0; i < 4; i++) {
            int c = tid + i * 256;
            int r = c >> 4, q = (c & 15) * 8;
            cp16(Bs + buf * WG_B_STG + r * 136 + q,
                 Bp + (size_t)(krow + r) * S + s0 + q);
        }
    };

    prefetch(0, 0); CP_COMMIT;
    if (NIT > 1) { prefetch(1, 1); CP_COMMIT; }

    int buf = 0;
    for (int it = 0; it < NIT; it++) {
        if (it + 1 < NIT) CP_WAIT1; else CP_WAIT0;
        __syncthreads();
        #pragma unroll
        for (int ks = 0; ks < 4; ks++) {
            wmma::fragment<wmma::matrix_a, 16, 16, 16, __nv_bfloat16, wmma::row_major> af[4];
            #pragma unroll
            for (int i = 0; i < 4; i++)
                wmma::load_matrix_sync(af[i], As + buf * WG_A_STG + (wm * 64 + i * 16) * 72 + ks * 16, 72);
            wmma::fragment<wmma::matrix_b, 16, 16, 16, __nv_bfloat16, wmma::row_major> bf[2];
            #pragma unroll
            for (int j = 0; j < 2; j++)
                wmma::load_matrix_sync(bf[j], Bs + buf * WG_B_STG + (ks * 16) * 136 + wn * 32 + j * 16, 136);
            #pragma unroll
            for (int i = 0; i < 4; i++)
                #pragma unroll
                for (int j = 0; j < 2; j++)
                    wmma::mma_sync(acc[i][j], af[i], bf[j], acc[i][j]);
        }
        if (it + 2 < NIT) {
            prefetch(it + 2, (buf + 2) % 3);
            CP_COMMIT;
        }
        buf = (buf + 1) % 3;
    }

    __syncthreads();

    if (MODE == 0) {
        #pragma unroll
        for (int i = 0; i < 4; i++)
            #pragma unroll
            for (int j = 0; j < 2; j++)
                wmma::store_matrix_sync(Cs + (wm * 64 + i * 16) * 132 + wn * 32 + j * 16,
                                        acc[i][j], 132, wmma::mem_row_major);
        __syncthreads();
        float* Ob = outF + (size_t)m0 * S;
        #pragma unroll
        for (int it = 0; it < 16; it++) {
            int idx = tid + it * 256;
            int r = idx >> 5, c4 = idx & 31;
            float bv = bias[m0 + r];
            float4 v = *reinterpret_cast<const float4*>(&Cs[r * 132 + c4 * 4]);
            v.x += bv; v.y += bv; v.z += bv; v.w += bv;
            *reinterpret_cast<float4*>(&Ob[(size_t)r * S + s0 + c4 * 4]) = v;
        }
    } else {
        #pragma unroll
        for (int i = 0; i < 4; i++)
            #pragma unroll
            for (int j = 0; j < 2; j++)
                wmma::store_matrix_sync(Cs + (wn * 32 + j * 16) * 136 + wm * 64 + i * 16,
                                        acc[i][j], 136, wmma::mem_col_major);
        __syncthreads();

        int dg = tid & 15;
        int gmb = m0 + dg * 8;
        float bias8[8];
        #pragma unroll
        for (int e = 0; e < 8; e++) bias8[e] = bias[gmb + e];

        float sc;
        int db = gmb & 63;
        __nv_bfloat16* hbase;
        if (MODE == 1) {
            int hb = gmb >> 6;
            sc = qScale;
            hbase = outB + ((size_t)hb * S + s0) * 64 + db;
        } else {
            int sel = gmb >> 8, head = (gmb >> 6) & 3;
            sc = (sel == 0) ? qScale : 1.f;
            hbase = outB + (((size_t)sel * 4 + head) * 512) * 4096 + db;
        }

        #pragma unroll
        for (int it = 0; it < 8; it++) {
            int sl = it * 16 + (tid >> 4);
            float4 lo = *reinterpret_cast<const float4*>(&Cs[sl * 136 + dg * 8]);
            float4 hi = *reinterpret_cast<const float4*>(&Cs[sl * 136 + dg * 8 + 4]);
            float f[8] = {lo.x, lo.y, lo.z, lo.w, hi.x, hi.y, hi.z, hi.w};
            #pragma unroll
            for (int e = 0; e < 8; e++) f[e] = (f[e] + bias8[e]) * sc;
            uint4 u;
            u.x = pack2(f[0], f[1]);
            u.y = pack2(f[2], f[3]);
            u.z = pack2(f[4], f[5]);
            u.w = pack2(f[6], f[7]);
            size_t off;
            if (MODE == 1) {
                off = (size_t)sl * 64;
            } else {
                int s = s0 + sl;
                int d5 = s & 31, w5 = (s >> 5) & 31, h5 = s >> 10;
                int window = ((h5 >> 2) * 8 + (w5 >> 2)) * 8 + (d5 >> 2);
                int token  = (((h5 & 3) * 4 + (w5 & 3)) * 4 + (d5 & 3));
                off = (size_t)window * 4096 + token * 64;
            }
            *reinterpret_cast<uint4*>(hbase + off) = u;
        }
    }
}

// =========================================================================
// Local windowed attention — fused raw-bf16 attnB store in epilogue
// =========================================================================
__global__ void __launch_bounds__(128) local_attn_w_kernel(
    const __nv_bfloat16* __restrict__ qkvB, const float* __restrict__ x,
    float* __restrict__ attn, __nv_bfloat16* __restrict__ attnB,
    float* __restrict__ praw, float* __restrict__ part) {
    __shared__ __align__(16) __nv_bfloat16 QP[64 * 72];
    __shared__ __align__(16) __nv_bfloat16 Ks[64 * 72];
    __shared__ __align__(16) __nv_bfloat16 Vs[64 * 72];
    __shared__ __align__(16) float Sf[64 * 68];
    __shared__ float linv[64];
    __shared__ float rs[4], rss[4];

    int w = blockIdx.x, head = blockIdx.y;
    int tid = threadIdx.x, warp = tid >> 5;

    size_t base = ((size_t)head * 512 + w) * 4096;
    size_t step = (size_t)4 * 512 * 4096;
    const uint4* Qg = (const uint4*)(qkvB + base);
    const uint4* Kg = (const uint4*)(qkvB + base + step);
    const uint4* Vg = (const uint4*)(qkvB + base + 2 * step);

    #pragma unroll
    for (int i = 0; i < 4; i++) {
        int c = tid + i * 128;
        int r = c >> 3, q = c & 7;
        ((uint4*)(QP + r * 72))[q] = Qg[c];
        ((uint4*)(Ks + r * 72))[q] = Kg[c];
        ((uint4*)(Vs + r * 72))[q] = Vg[c];
    }
    __syncthreads();

    {
        int m = warp * 16;
        wmma::fragment<wmma::accumulator, 16, 16, 16, float> acc[4];
        #pragma unroll
        for (int j = 0; j < 4; j++) wmma::fill_fragment(acc[j], 0.f);
        #pragma unroll
        for (int kd = 0; kd < 4; kd++) {
            wmma::fragment<wmma::matrix_a, 16, 16, 16, __nv_bfloat16, wmma::row_major> af;
            wmma::load_matrix_sync(af, QP + m * 72 + kd * 16, 72);
            #pragma unroll
            for (int j = 0; j < 4; j++) {
                wmma::fragment<wmma::matrix_b, 16, 16, 16, __nv_bfloat16, wmma::col_major> bf;
                wmma::load_matrix_sync(bf, Ks + (j * 16) * 72 + kd * 16, 72);
                wmma::mma_sync(acc[j], af, bf, acc[j]);
            }
        }
        #pragma unroll
        for (int j = 0; j < 4; j++)
            wmma::store_matrix_sync(Sf + m * 68 + j * 16, acc[j], 68, wmma::mem_row_major);
    }
    __syncthreads();

    {
        int r = tid >> 1, hf = tid & 1;
        const float* srow = Sf + r * 68 + hf * 32;
        float ls = 0.f;
        __nv_bfloat16* prow = QP + r * 72 + hf * 32;
        #pragma unroll
        for (int j = 0; j < 32; j++) {
            float p = __expf(srow[j]);
            ls += p;
            prow[j] = __float2bfloat16(p);
        }
        ls += __shfl_xor_sync(0xffffffffu, ls, 1);
        if (hf == 0) linv[r] = 1.f / ls;
    }
    __syncthreads();

    {
        int m = warp * 16;
        wmma::fragment<wmma::accumulator, 16, 16, 16, float> acc[4];
        #pragma unroll
        for (int j = 0; j < 4; j++) wmma::fill_fragment(acc[j], 0.f);
        #pragma unroll
        for (int kk = 0; kk < 4; kk++) {
            wmma::fragment<wmma::matrix_a, 16, 16, 16, __nv_bfloat16, wmma::row_major> af;
            wmma::load_matrix_sync(af, QP + m * 72 + kk * 16, 72);
            #pragma unroll
            for (int j = 0; j < 4; j++) {
                wmma::fragment<wmma::matrix_b, 16, 16, 16, __nv_bfloat16, wmma::row_major> bf;
                wmma::load_matrix_sync(bf, Vs + (kk * 16) * 72 + j * 16, 72);
                wmma::mma_sync(acc[j], af, bf, acc[j]);
            }
        }
        #pragma unroll
        for (int j = 0; j < 4; j++)
            wmma::store_matrix_sync(Sf + m * 68 + j * 16, acc[j], 68, wmma::mem_row_major);
    }
    __syncthreads();

    int wh = w >> 6, ww = (w >> 3) & 7, wd = w & 7;
    int base_s = wh * 4096 + ww * 128 + wd * 4;
    int chb = head * 64;
    float s_acc = 0.f, ss_acc = 0.f;
    #pragma unroll
    for (int it = 0; it < 8; it++) {
        int idx = tid + it * 128;
        int d = idx >> 4, tg = idx & 15;
        int i_ = tg >> 2, j_ = tg & 3;
        int s = base_s + i_ * 1024 + j_ * 32;
        int t0 = tg * 4;
        size_t g = ((size_t)(chb + d)) * SV + s;
        float4 xv = *reinterpret_cast<const float4*>(x + g);
        float4 ov;
        ov.x = fmaf(Sf[(t0 + 0) * 68 + d], linv[t0 + 0], xv.x);
        ov.y = fmaf(Sf[(t0 + 1) * 68 + d], linv[t0 + 1], xv.y);
        ov.z = fmaf(Sf[(t0 + 2) * 68 + d], linv[t0 + 2], xv.z);
        ov.w = fmaf(Sf[(t0 + 3) * 68 + d], linv[t0 + 3], xv.w);
        *reinterpret_cast<float4*>(attn + g) = ov;
        uint2 rb;
        rb.x = pack2(ov.x, ov.y);
        rb.y = pack2(ov.z, ov.w);
        *reinterpret_cast<uint2*>(attnB + g) = rb;
        float ps = ov.x + ov.y + ov.z + ov.w;
        s_acc  += ps;
        ss_acc += ov.x*ov.x + ov.y*ov.y + ov.z*ov.z + ov.w*ov.w;
        #pragma unroll
        for (int o = 8; o; o >>= 1) ps += __shfl_down_sync(0xffffffffu, ps, o);
        if ((tid & 15) == 0)
            praw[((size_t)(chb + d)) * 512 + w] = ps * (1.f / 64.f);
    }
    #pragma unroll
    for (int o = 16; o; o >>= 1) {
        s_acc  += __shfl_down_sync(0xffffffffu, s_acc, o);
        ss_acc += __shfl_down_sync(0xffffffffu, ss_acc, o);
    }
    if ((tid & 31) == 0) { rs[warp] = s_acc; rss[warp] = ss_acc; }
    __syncthreads();
    if (tid == 0) {
        size_t pi = (size_t)head * 512 + w;
        part[pi * 2 + 0] = rs[0] + rs[1] + rs[2] + rs[3];
        part[pi * 2 + 1] = rss[0] + rss[1] + rss[2] + rss[3];
    }
}

// =========================================================================
// Global attention — per-batch pointers
// =========================================================================
#define GA_SMEM 109056

__global__ void __launch_bounds__(256, 2) gattn_kernel(
    const __nv_bfloat16* __restrict__ q2T, const __nv_bfloat16* __restrict__ kvT,
    const float* __restrict__ attn,
    const float* __restrict__ A1, const float* __restrict__ D1,
    __nv_bfloat16* __restrict__ ghi, __nv_bfloat16* __restrict__ glo) {
    extern __shared__ __align__(16) char sm[];
    __nv_bfloat16* Qs = (__nv_bfloat16*)sm;
    __nv_bfloat16* Ks = Qs + 128 * 72;
    __nv_bfloat16* Vs = Ks + 2 * 64 * 72;
    __nv_bfloat16* Ps = Vs + 2 * 64 * 72;
    float* Sf   = (float*)(Ps + 128 * 72);
    float* lrow = Sf + 128 * 68;

    int tid = threadIdx.x, warp = tid >> 5;
    int h = blockIdx.y;
    int s0 = blockIdx.x * 128;

    const uint4* Qg = (const uint4*)(q2T + ((size_t)h * SV + s0) * 64);
    const __nv_bfloat16* Kg = kvT + ((size_t)h * 512) * 64;
    const __nv_bfloat16* Vg = kvT + ((size_t)(4 + h) * 512) * 64;

    auto prefetchKV = [&](int ch, int b) {
        #pragma unroll
        for (int i = 0; i < 2; i++) {
            int idx = tid + i * 256;
            int r = idx >> 3, c = (idx & 7) * 8;
            cp16(Ks + b * 4608 + r * 72 + c, Kg + (size_t)(ch * 64 + r) * 64 + c);
            cp16(Vs + b * 4608 + r * 72 + c, Vg + (size_t)(ch * 64 + r) * 64 + c);
        }
    };

    prefetchKV(0, 0); CP_COMMIT;

    #pragma unroll
    for (int i = 0; i < 4; i++) {
        int idx = tid + i * 256;
        int r = idx >> 3, c = idx & 7;
        ((uint4*)(Qs + r * 72))[c] = Qg[r * 8 + c];
    }
    if (tid < 128) lrow[tid] = 0.f;

    int pm = warp >> 1, pn = warp & 1;
    wmma::fragment<wmma::accumulator, 16, 16, 16, float> acc_o[2][2];
    #pragma unroll
    for (int i = 0; i < 2; i++)
        #pragma unroll
        for (int j = 0; j < 2; j++) wmma::fill_fragment(acc_o[i][j], 0.f);

    for (int ch = 0; ch < 8; ch++) {
        int b = ch & 1;
        CP_WAIT0;
        __syncthreads();

        {
            int m = warp * 16;
            wmma::fragment<wmma::accumulator, 16, 16, 16, float> acc[4];
            #pragma unroll
            for (int j = 0; j < 4; j++) wmma::fill_fragment(acc[j], 0.f);
            #pragma unroll
            for (int kd = 0; kd < 4; kd++) {
                wmma::fragment<wmma::matrix_a, 16, 16, 16, __nv_bfloat16, wmma::row_major> af;
                wmma::load_matrix_sync(af, Qs + m * 72 + kd * 16, 72);
                #pragma unroll
                for (int j = 0; j < 4; j++) {
                    wmma::fragment<wmma::matrix_b, 16, 16, 16, __nv_bfloat16, wmma::col_major> bf;
                    wmma::load_matrix_sync(bf, Ks + b * 4608 + (j * 16) * 72 + kd * 16, 72);
                    wmma::mma_sync(acc[j], af, bf, acc[j]);
                }
            }
            #pragma unroll
            for (int j = 0; j < 4; j++)
                wmma::store_matrix_sync(Sf + m * 68 + j * 16, acc[j], 68, wmma::mem_row_major);
        }
        __syncthreads();

        {
            int r = tid >> 1, hf = tid & 1;
            const float* srow = Sf + r * 68 + hf * 32;
            float ls = 0.f;
            __nv_bfloat16* prow = Ps + r * 72 + hf * 32;
            #pragma unroll
            for (int j = 0; j < 32; j++) {
                float p = __expf(srow[j]);
                ls += p;
                prow[j] = __float2bfloat16(p);
            }
            ls += __shfl_xor_sync(0xffffffffu, ls, 1);
            if (hf == 0) lrow[r] += ls;
        }
        __syncthreads();

        if (ch + 1 < 8) {
            prefetchKV(ch + 1, b ^ 1);
            CP_COMMIT;
        }

        {
            #pragma unroll
            for (int kk = 0; kk < 4; kk++) {
                wmma::fragment<wmma::matrix_a, 16, 16, 16, __nv_bfloat16, wmma::row_major> af[2];
                #pragma unroll
                for (int i = 0; i < 2; i++)
                    wmma::load_matrix_sync(af[i], Ps + (pm * 32 + i * 16) * 72 + kk * 16, 72);
                wmma::fragment<wmma::matrix_b, 16, 16, 16, __nv_bfloat16, wmma::row_major> bf[2];
                #pragma unroll
                for (int j = 0; j < 2; j++)
                    wmma::load_matrix_sync(bf[j], Vs + b * 4608 + (kk * 16) * 72 + pn * 32 + j * 16, 72);
                #pragma unroll
                for (int i = 0; i < 2; i++)
                    #pragma unroll
                    for (int j = 0; j < 2; j++)
                        wmma::mma_sync(acc_o[i][j], af[i], bf[j], acc_o[i][j]);
            }
        }
    }

    __syncthreads();
    #pragma unroll
    for (int i = 0; i < 2; i++)
        #pragma unroll
        for (int j = 0; j < 2; j++)
            wmma::store_matrix_sync(Sf + (pm * 32 + i * 16) * 68 + pn * 32 + j * 16,
                                    acc_o[i][j], 68, wmma::mem_row_major);
    __syncthreads();

    #pragma unroll
    for (int i = 0; i < 32; i++) {
        int idx = tid + i * 256;
        int r = idx & 127, d = idx >> 7;
        int cch = h * 64 + d;
        float v = Sf[r * 68 + d] / lrow[r];
        size_t gi = ((size_t)cch) * SV + s0 + r;
        float t = v + fmaf(A1[cch], attn[gi], D1[cch]);
        __nv_bfloat16 hi = __float2bfloat16(t);
        ghi[gi] = hi;
        glo[gi] = __float2bfloat16(t - __bfloat162float(hi));
    }
}

// =========================================================================
// host launch — 2 batch streams + 2 side streams
// =========================================================================
extern "C" void kernel_launch(void* const* d_in, const int* in_sizes, int n_in,
                              void* d_out, int out_size) {
    const float* x      = (const float*)d_in[0];
    const float* qkv_w  = (const float*)d_in[1];
    const float* qkv_b  = (const float*)d_in[2];
    const float* norm_w = (const float*)d_in[3];
    const float* norm_b = (const float*)d_in[4];
    const float* anorm_w= (const float*)d_in[5];
    const float* anorm_b= (const float*)d_in[6];
    const float* dnorm_w= (const float*)d_in[7];
    const float* dnorm_b= (const float*)d_in[8];
    const float* q_w    = (const float*)d_in[9];
    const float* q_b    = (const float*)d_in[10];
    const float* kv_w   = (const float*)d_in[11];
    const float* kv_b   = (const float*)d_in[12];
    const float* proj_w = (const float*)d_in[13];
    const float* proj_b = (const float*)d_in[14];
    float* out = (float*)d_out;

    float *attn, *praw, *pnorm, *part, *part2, *aff, *qkvb2, *qb2;
    __nv_bfloat16 *xB, *qkvB, *attnB, *ghi, *glo, *pooledB, *q2T, *kvT;
    __nv_bfloat16 *Wqkv2B, *Wq2B, *WkvB, *WprojB;
    cudaGetSymbolAddress((void**)&attn,    g_attn);
    cudaGetSymbolAddress((void**)&praw,    g_praw);
    cudaGetSymbolAddress((void**)&pnorm,   g_pnorm);
    cudaGetSymbolAddress((void**)&xB,      g_xB);
    cudaGetSymbolAddress((void**)&qkvB,    g_qkvB);
    cudaGetSymbolAddress((void**)&attnB,   g_attnB);
    cudaGetSymbolAddress((void**)&ghi,     g_ghi);
    cudaGetSymbolAddress((void**)&glo,     g_glo);
    cudaGetSymbolAddress((void**)&pooledB, g_pooledB);
    cudaGetSymbolAddress((void**)&q2T,     g_q2T);
    cudaGetSymbolAddress((void**)&kvT,     g_kvT);
    cudaGetSymbolAddress((void**)&Wqkv2B,  g_Wqkv2B);
    cudaGetSymbolAddress((void**)&Wq2B,    g_Wq2B);
    cudaGetSymbolAddress((void**)&WkvB,    g_WkvB);
    cudaGetSymbolAddress((void**)&WprojB,  g_WprojB);
    cudaGetSymbolAddress((void**)&qkvb2,   g_qkvb2);
    cudaGetSymbolAddress((void**)&qb2,     g_qb2);
    cudaGetSymbolAddress((void**)&part,    g_part);
    cudaGetSymbolAddress((void**)&part2,   g_part2);
    cudaGetSymbolAddress((void**)&aff,     g_aff);

    static cudaStream_t s1 = nullptr, s2 = nullptr, s3 = nullptr;
    static cudaEvent_t ev0, evW, evDone;
    static cudaEvent_t evA1[2], evKV[2];
    static bool init_done = false;
    if (!init_done) {
        cudaFuncSetAttribute(gattn_kernel, cudaFuncAttributeMaxDynamicSharedMemorySize, GA_SMEM);
        cudaFuncSetAttribute(wgemm3_kernel<0>, cudaFuncAttributeMaxDynamicSharedMemorySize, WG_SMEM);
        cudaFuncSetAttribute(wgemm3_kernel<1>, cudaFuncAttributeMaxDynamicSharedMemorySize, WG_SMEM);
        cudaFuncSetAttribute(wgemm3_kernel<2>, cudaFuncAttributeMaxDynamicSharedMemorySize, WG_SMEM);
        cudaStreamCreateWithFlags(&s1, cudaStreamNonBlocking);
        cudaStreamCreateWithFlags(&s2, cudaStreamNonBlocking);
        cudaStreamCreateWithFlags(&s3, cudaStreamNonBlocking);
        cudaEventCreateWithFlags(&ev0,    cudaEventDisableTiming);
        cudaEventCreateWithFlags(&evW,    cudaEventDisableTiming);
        cudaEventCreateWithFlags(&evDone, cudaEventDisableTiming);
        for (int i = 0; i < 2; i++) {
            cudaEventCreateWithFlags(&evA1[i], cudaEventDisableTiming);
            cudaEventCreateWithFlags(&evKV[i], cudaEventDisableTiming);
        }
        init_done = true;
    }

    // fork side streams from capture origin
    cudaEventRecord(ev0, 0);
    cudaStreamWaitEvent(s1, ev0, 0);
    cudaStreamWaitEvent(s2, ev0, 0);
    cudaStreamWaitEvent(s3, ev0, 0);

    // weights convert once on s2
    convert_weights_kernel<<<1280, 256, 0, s2>>>(kv_w, proj_w, WkvB, WprojB);
    cudaEventRecord(evW, s2);

    for (int n = 0; n < NB; n++) {
        cudaStream_t mSt = (n == 0) ? (cudaStream_t)0 : s1;
        cudaStream_t sSt = (n == 0) ? s2 : s3;
        const float* x_n       = x      + (size_t)n * 256 * SV;
        float* attn_n          = attn   + (size_t)n * 256 * SV;
        float* praw_n          = praw   + (size_t)n * 256 * 512;
        float* pnorm_n         = pnorm  + (size_t)n * 256 * 512;
        __nv_bfloat16* xB_n    = xB     + (size_t)n * 256 * SV;
        __nv_bfloat16* qkvB_n  = qkvB   + (size_t)n * 768 * SV;
        __nv_bfloat16* attnB_n = attnB  + (size_t)n * 256 * SV;
        __nv_bfloat16* ghi_n   = ghi    + (size_t)n * 256 * SV;
        __nv_bfloat16* glo_n   = glo    + (size_t)n * 256 * SV;
        __nv_bfloat16* pooledB_n = pooledB + (size_t)n * 256 * 512;
        __nv_bfloat16* q2T_n   = q2T    + (size_t)n * 4 * SV * 64;
        __nv_bfloat16* kvT_n   = kvT    + (size_t)n * 8 * 512 * 64;
        __nv_bfloat16* Wqkv2_n = Wqkv2B + (size_t)n * 768 * 256;
        __nv_bfloat16* Wq2_n   = Wq2B   + (size_t)n * 256 * 256;
        float* qkvb2_n = qkvb2 + n * 768;
        float* qb2_n   = qb2   + n * 256;
        float* part_n  = part  + (size_t)n * 2048 * 2;
        float* part2_n = part2 + (size_t)n * 64 * 2;
        float* A0n = aff + n * 256;          float* D0n = aff + 512 + n * 256;
        float* A1n = aff + 1024 + n * 256;   float* D1n = aff + 1536 + n * 256;
        float* A2n = aff + 2048 + n * 256;   float* D2n = aff + 2560 + n * 256;
        float* out_n = out + (size_t)n * 256 * SV;

        // main: x stats + fold + qkv GEMM + local attention (emits attnB too)
        reduce1x_kernel<<<512, 256, 0, mSt>>>(x_n, 256L * SV / 4, part_n, xB_n);
        stats2affine_kernel<<<1, 256, 0, mSt>>>(part_n, 512, norm_w, norm_b, A0n, D0n,
                                                1.f / (256.f * 32768.f));
        fold_kernel<<<768, 256, 0, mSt>>>(qkv_w, qkv_b, A0n, D0n, Wqkv2_n, qkvb2_n);
        wgemm3_kernel<2><<<dim3(6, 256), 256, WG_SMEM, mSt>>>(
            Wqkv2_n, xB_n, xB_n, qkvb2_n, nullptr, qkvB_n, 768, (int)SV, 256, SCALE_INV);
        local_attn_w_kernel<<<dim3(512, NH), 128, 0, mSt>>>(
            qkvB_n, x_n, attn_n, attnB_n, praw_n, part_n);

        // main: anorm affine + q fold
        stats2affine_kernel<<<1, 256, 0, mSt>>>(part_n, 2048, anorm_w, anorm_b, A1n, D1n,
                                                1.f / (256.f * 32768.f));
        cudaEventRecord(evA1[n], mSt);
        fold_kernel<<<256, 256, 0, mSt>>>(q_w, q_b, A1n, D1n, Wq2_n, qb2_n);

        // side: pooled chain (needs A1 + praw, both done before evA1) + kv GEMM
        cudaStreamWaitEvent(sSt, evA1[n], 0);
        reduce1p_kernel<<<32, 256, 0, sSt>>>(praw_n, A1n, D1n, 256L * 512 / 4, part2_n, pnorm_n);
        stats2affine_kernel<<<1, 256, 0, sSt>>>(part2_n, 32, dnorm_w, dnorm_b, A2n, D2n,
                                                1.f / (256.f * 512.f));
        convert_pooled_kernel<<<128, 256, 0, sSt>>>(pnorm_n, A2n, D2n, pooledB_n);
        if (n == 1) cudaStreamWaitEvent(sSt, evW, 0);
        wgemm3_kernel<1><<<dim3(4, 4), 256, WG_SMEM, sSt>>>(
            WkvB, pooledB_n, pooledB_n, kv_b, nullptr, kvT_n, 512, 512, 256, 1.f);
        cudaEventRecord(evKV[n], sSt);

        // main: q GEMM -> gattn -> proj (attnB ready in-order on mSt)
        wgemm3_kernel<1><<<dim3(2, 256), 256, WG_SMEM, mSt>>>(
            Wq2_n, attnB_n, attnB_n, qb2_n, nullptr, q2T_n, 256, (int)SV, 256, SCALE_INV);
        cudaStreamWaitEvent(mSt, evKV[n], 0);
        gattn_kernel<<<dim3(256, NH), 256, GA_SMEM, mSt>>>(
            q2T_n, kvT_n, attn_n, A1n, D1n, ghi_n, glo_n);
        cudaStreamWaitEvent(mSt, evW, 0);
        wgemm3_kernel<0><<<dim3(2, 256), 256, WG_SMEM, mSt>>>(
            WprojB, ghi_n, glo_n, proj_b, out_n, nullptr, 256, (int)SV, 768, 1.f);
    }

    // join batch1 main stream into default
    cudaEventRecord(evDone, s1);
    cudaStreamWaitEvent(0, evDone, 0);
}